// round 14
// baseline (speedup 1.0000x reference)
#include <cuda_runtime.h>
#include <cuda_fp16.h>
#include <cstdint>

// ---------------- static scratch (no allocations allowed) ----------------
#define MAXN 100000
#define MAXE 1600000
#define SCAN_B 1024

__device__ float  g_dinv[MAXN];
__device__ float  g_agg [MAXN * 128];     // agg results (fp32)
__device__ float  g_out1[MAXN * 256];     // layer-1 output
__device__ __half g_h16 [MAXN * 128];     // fp16 PRESCALED gather buffer
__device__ int    g_deg [MAXN];           // zero at entry; re-zeroed in k_finalize
__device__ int    g_excl[MAXN];
__device__ int    g_btot[128];
__device__ int    g_rowp[MAXN + 1];
__device__ int    g_cur [MAXN];
__device__ int    g_csrc[MAXE];

// ---------------- fp16 helpers ----------------
__device__ __forceinline__ void acc8(float* acc, uint4 r) {
    const __half2* p = reinterpret_cast<const __half2*>(&r);
#pragma unroll
    for (int i = 0; i < 4; i++) {
        float2 f = __half22float2(p[i]);
        acc[2 * i]     += f.x;
        acc[2 * i + 1] += f.y;
    }
}

// xh[row] = fp16( x[row] * dinv[row] )   (prescaled gather buffer)
__global__ void k_f2h_scaled(const float* __restrict__ x,
                             const float* __restrict__ dinv,
                             __half* __restrict__ xh, int n4) {
    int i = blockIdx.x * blockDim.x + threadIdx.x;
    if (i >= n4) return;
    float s = dinv[i >> 5];
    float4 v = reinterpret_cast<const float4*>(x)[i];
    __half2 p0 = __floats2half2_rn(v.x * s, v.y * s);
    __half2 p1 = __floats2half2_rn(v.z * s, v.w * s);
    uint2 r;
    r.x = *reinterpret_cast<uint32_t*>(&p0);
    r.y = *reinterpret_cast<uint32_t*>(&p1);
    reinterpret_cast<uint2*>(xh)[i] = r;
}

// ---------------- CSR build ----------------
__global__ void k_hist(const int* __restrict__ dst, int* deg, int E) {
    int e = blockIdx.x * blockDim.x + threadIdx.x;
    if (e < E) atomicAdd(&deg[dst[e]], 1);
}

__global__ void k_scan_blocks(const int* __restrict__ deg, int* excl,
                              int* btot, int n) {
    __shared__ int sh[SCAN_B];
    int t = threadIdx.x;
    int i = blockIdx.x * SCAN_B + t;
    int v = (i < n) ? deg[i] : 0;
    sh[t] = v;
    __syncthreads();
    for (int off = 1; off < SCAN_B; off <<= 1) {
        int add = (t >= off) ? sh[t - off] : 0;
        __syncthreads();
        sh[t] += add;
        __syncthreads();
    }
    if (i < n) excl[i] = sh[t] - v;
    if (t == SCAN_B - 1) btot[blockIdx.x] = sh[t];
}

__global__ void k_scan_tops(int* btot, int nb) {   // 1 block, 128 threads
    __shared__ int sh[128];
    int t = threadIdx.x;
    int v = (t < nb) ? btot[t] : 0;
    sh[t] = v;
    __syncthreads();
    for (int off = 1; off < 128; off <<= 1) {
        int add = (t >= off) ? sh[t - off] : 0;
        __syncthreads();
        sh[t] += add;
        __syncthreads();
    }
    if (t < nb) btot[t] = sh[t] - v;
}

__global__ void k_finalize(int* deg, const int* __restrict__ excl,
                           const int* __restrict__ btot,
                           int* rowp, int* cur, float* dinv, int n) {
    int i = blockIdx.x * blockDim.x + threadIdx.x;
    if (i >= n) return;
    int dg = deg[i];
    int rp = excl[i] + btot[i >> 10];
    rowp[i] = rp;
    cur[i]  = rp;
    dinv[i] = rsqrtf((float)dg + 1.0f);   // +1 self-loop
    if (i == n - 1) rowp[n] = rp + dg;
    deg[i] = 0;                            // ready for next replay
}

__global__ void k_fillcsr(const int* __restrict__ src, const int* __restrict__ dst,
                          int* cur, int* csrc, int E) {
    int e = blockIdx.x * blockDim.x + threadIdx.x;
    if (e >= E) return;
    int pos = atomicAdd(&cur[dst[e]], 1);
    csrc[pos] = src[e];
}

// -------- CSR aggregation: HALF-WARP per dst node, uint4 lanes --------
// out[d] = dinv[d] * ( p[d] + sum_s p[s] ),  p = prescaled fp16 rows.
// lanes 0-15 -> node 2w, lanes 16-31 -> node 2w+1. Each lane: 16B (8 halfs).
// One LDG.128 per gather serves two rows -> 2x lines-in-flight per warp.
template <bool FINAL>
__global__ void k_agg16(const int* __restrict__ rowp, const int* __restrict__ csrc,
                        const float* __restrict__ dinv, const __half* __restrict__ h,
                        float* __restrict__ out,
                        const float* __restrict__ bias, const float* __restrict__ ap,
                        float* __restrict__ out2, int n) {
    int gtid = blockIdx.x * blockDim.x + threadIdx.x;
    int w = gtid >> 5, lane = gtid & 31;
    int half = lane >> 4, sub = lane & 15;
    int d = w * 2 + half;
    if (d >= n) return;

    float acc[8];
    {
        uint4 rs = reinterpret_cast<const uint4*>(h + (size_t)d * 128)[sub];
        const __half2* p = reinterpret_cast<const __half2*>(&rs);
#pragma unroll
        for (int i = 0; i < 4; i++) {
            float2 f = __half22float2(p[i]);
            acc[2 * i] = f.x; acc[2 * i + 1] = f.y;
        }
    }

    int j = rowp[d], end = rowp[d + 1];
    for (; j + 8 <= end; j += 8) {
        int s[8];
#pragma unroll
        for (int u = 0; u < 8; u++) s[u] = csrc[j + u];
        uint4 r[8];
#pragma unroll
        for (int u = 0; u < 8; u++)
            r[u] = reinterpret_cast<const uint4*>(h + (size_t)s[u] * 128)[sub];
#pragma unroll
        for (int u = 0; u < 8; u++) acc8(acc, r[u]);
    }
    if (j + 4 <= end) {
        int s[4];
#pragma unroll
        for (int u = 0; u < 4; u++) s[u] = csrc[j + u];
        uint4 r[4];
#pragma unroll
        for (int u = 0; u < 4; u++)
            r[u] = reinterpret_cast<const uint4*>(h + (size_t)s[u] * 128)[sub];
#pragma unroll
        for (int u = 0; u < 4; u++) acc8(acc, r[u]);
        j += 4;
    }
    for (; j < end; j++) {
        uint4 r = reinterpret_cast<const uint4*>(h + (size_t)csrc[j] * 128)[sub];
        acc8(acc, r);
    }

    float dd = dinv[d];
#pragma unroll
    for (int i = 0; i < 8; i++) acc[i] *= dd;

    if (FINAL) {
        float a = *ap;
        float4 b0 = *reinterpret_cast<const float4*>(bias + sub * 8);
        float4 b1 = *reinterpret_cast<const float4*>(bias + sub * 8 + 4);
        acc[0] += b0.x; acc[1] += b0.y; acc[2] += b0.z; acc[3] += b0.w;
        acc[4] += b1.x; acc[5] += b1.y; acc[6] += b1.z; acc[7] += b1.w;
#pragma unroll
        for (int i = 0; i < 8; i++) acc[i] = acc[i] >= 0.f ? acc[i] : a * acc[i];
        float* o2 = out2 + (size_t)d * 128 + sub * 8;
        *reinterpret_cast<float4*>(o2)     = make_float4(acc[0], acc[1], acc[2], acc[3]);
        *reinterpret_cast<float4*>(o2 + 4) = make_float4(acc[4], acc[5], acc[6], acc[7]);
    }
    float* o = out + (size_t)d * 128 + sub * 8;
    *reinterpret_cast<float4*>(o)     = make_float4(acc[0], acc[1], acc[2], acc[3]);
    *reinterpret_cast<float4*>(o + 4) = make_float4(acc[4], acc[5], acc[6], acc[7]);
}

// ------------- tf32 tensor-core GEMM, cp.async double-buffered -------------
__device__ __forceinline__ uint32_t f2tf32(float f) {
    uint32_t u;
    asm("cvt.rna.tf32.f32 %0, %1;" : "=r"(u) : "f"(f));
    return u;
}

__device__ __forceinline__ void mma_tf32(float* c, const uint32_t* a, const uint32_t* b) {
    asm volatile(
        "mma.sync.aligned.m16n8k8.row.col.f32.tf32.tf32.f32 "
        "{%0,%1,%2,%3}, {%4,%5,%6,%7}, {%8,%9}, {%0,%1,%2,%3};"
        : "+f"(c[0]), "+f"(c[1]), "+f"(c[2]), "+f"(c[3])
        : "r"(a[0]), "r"(a[1]), "r"(a[2]), "r"(a[3]),
          "r"(b[0]), "r"(b[1]));
}

__device__ __forceinline__ void cp16(void* smem_dst, const void* gsrc, bool valid) {
    uint32_t saddr = (uint32_t)__cvta_generic_to_shared(smem_dst);
    int sz = valid ? 16 : 0;
    asm volatile("cp.async.cg.shared.global [%0], [%1], 16, %2;"
                 :: "r"(saddr), "l"(gsrc), "r"(sz));
}
#define CP_COMMIT asm volatile("cp.async.commit_group;")
#define CP_WAIT(n) asm volatile("cp.async.wait_group %0;" :: "n"(n))

// EPI: 0 raw  1 prelu(acc+bias)  2 relu(acc+bias)  3 acc+bias
//      5 fp16(acc * dinv[row]) -> Ch  (prescaled gather buffer)
template <int EPI>
__global__ __launch_bounds__(256) void tgemm128(
    int M, int N, int K,
    const float* __restrict__ A, const float* __restrict__ B,
    const float* __restrict__ bias, const float* __restrict__ prelu_a,
    const float* __restrict__ dinvp,
    float* __restrict__ C, __half* __restrict__ Ch)
{
    constexpr int BK = 16;
    constexpr int LDSA = 20;
    constexpr int LDSN = 136;
    __shared__ float As[2][128 * LDSA];
    __shared__ float Bs[2][BK * LDSN];

    const int tid  = threadIdx.x;
    const int lane = tid & 31;
    const int wid  = tid >> 5;
    const int g    = lane >> 2;
    const int t    = lane & 3;

    const int warpM = (wid & 1) * 64;
    const int warpN = (wid >> 1) * 32;

    const int gRow = blockIdx.y * 128;
    const int gCol = blockIdx.x * 128;

    auto issueTile = [&](int k0, int s) {
#pragma unroll
        for (int i = 0; i < 2; i++) {
            int idx = tid + i * 256;
            int m  = idx >> 2, kq = (idx & 3) << 2;
            int gm = gRow + m;
            cp16(&As[s][m * LDSA + kq], &A[(size_t)gm * K + k0 + kq], gm < M);
        }
#pragma unroll
        for (int i = 0; i < 2; i++) {
            int idx = tid + i * 256;
            int k = idx >> 5, n4 = (idx & 31) << 2;
            cp16(&Bs[s][k * LDSN + n4], &B[(size_t)(k0 + k) * N + gCol + n4], true);
        }
    };

    float c[4][4][4];
#pragma unroll
    for (int mt = 0; mt < 4; mt++)
#pragma unroll
        for (int nt = 0; nt < 4; nt++)
#pragma unroll
            for (int i = 0; i < 4; i++) c[mt][nt][i] = 0.f;

    const int T = K / BK;
    issueTile(0, 0);
    CP_COMMIT;

    for (int it = 0; it < T; it++) {
        int s = it & 1;
        if (it + 1 < T) {
            issueTile((it + 1) * BK, s ^ 1);
            CP_COMMIT;
            CP_WAIT(1);
        } else {
            CP_WAIT(0);
        }
        __syncthreads();

#pragma unroll
        for (int kk = 0; kk < BK; kk += 8) {
            uint32_t af[4][4], bf[4][2];
#pragma unroll
            for (int mt = 0; mt < 4; mt++) {
                int m0 = warpM + mt * 16 + g;
                af[mt][0] = f2tf32(As[s][(m0    ) * LDSA + kk + t    ]);
                af[mt][1] = f2tf32(As[s][(m0 + 8) * LDSA + kk + t    ]);
                af[mt][2] = f2tf32(As[s][(m0    ) * LDSA + kk + t + 4]);
                af[mt][3] = f2tf32(As[s][(m0 + 8) * LDSA + kk + t + 4]);
            }
#pragma unroll
            for (int nt = 0; nt < 4; nt++) {
                int n0 = warpN + nt * 8 + g;
                bf[nt][0] = f2tf32(Bs[s][(kk + t    ) * LDSN + n0]);
                bf[nt][1] = f2tf32(Bs[s][(kk + t + 4) * LDSN + n0]);
            }
#pragma unroll
            for (int mt = 0; mt < 4; mt++)
#pragma unroll
                for (int nt = 0; nt < 4; nt++)
                    mma_tf32(c[mt][nt], af[mt], bf[nt]);
        }
        __syncthreads();
    }

    float a_val = 0.f;
    if (EPI == 1) a_val = *prelu_a;

#pragma unroll
    for (int mt = 0; mt < 4; mt++) {
        int r0 = gRow + warpM + mt * 16 + g;
        int r1 = r0 + 8;
        float s0 = 1.f, s1 = 1.f;
        if (EPI == 5) {
            if (r0 < M) s0 = dinvp[r0];
            if (r1 < M) s1 = dinvp[r1];
        }
#pragma unroll
        for (int nt = 0; nt < 4; nt++) {
            int col = gCol + warpN + nt * 8 + t * 2;
            float v0 = c[mt][nt][0], v1 = c[mt][nt][1];
            float v2 = c[mt][nt][2], v3 = c[mt][nt][3];

            if (EPI == 1 || EPI == 2 || EPI == 3) {
                float b0 = bias[col], b1 = bias[col + 1];
                v0 += b0; v1 += b1; v2 += b0; v3 += b1;
            }
            if (EPI == 1) {
                v0 = v0 >= 0.f ? v0 : a_val * v0;
                v1 = v1 >= 0.f ? v1 : a_val * v1;
                v2 = v2 >= 0.f ? v2 : a_val * v2;
                v3 = v3 >= 0.f ? v3 : a_val * v3;
            }
            if (EPI == 2) {
                v0 = fmaxf(v0, 0.f); v1 = fmaxf(v1, 0.f);
                v2 = fmaxf(v2, 0.f); v3 = fmaxf(v3, 0.f);
            }

            if (EPI == 5) {
                if (r0 < M)
                    *reinterpret_cast<__half2*>(&Ch[(size_t)r0 * N + col]) =
                        __floats2half2_rn(v0 * s0, v1 * s0);
                if (r1 < M)
                    *reinterpret_cast<__half2*>(&Ch[(size_t)r1 * N + col]) =
                        __floats2half2_rn(v2 * s1, v3 * s1);
            } else {
                if (r0 < M)
                    *reinterpret_cast<float2*>(&C[(size_t)r0 * N + col]) = make_float2(v0, v1);
                if (r1 < M)
                    *reinterpret_cast<float2*>(&C[(size_t)r1 * N + col]) = make_float2(v2, v3);
            }
        }
    }
}

// ---- fused proj head: proj = relu(A@fc1 + b1h) @ fc2 + b2h, hidden in smem ----
__global__ __launch_bounds__(256) void k_proj(
    int M,
    const float* __restrict__ A,
    const float* __restrict__ fc1w, const float* __restrict__ fc1b,
    const float* __restrict__ fc2w, const float* __restrict__ fc2b,
    float* __restrict__ C)
{
    constexpr int BK = 16, LDSA = 20, LDSN = 136, LDH = 132, K = 128, N = 128;
    extern __shared__ float sm[];
    float* As = sm;
    float* Bs = As + 2 * 128 * LDSA;
    float* H  = Bs + 2 * BK * LDSN;

    const int tid  = threadIdx.x;
    const int lane = tid & 31;
    const int wid  = tid >> 5;
    const int g    = lane >> 2;
    const int t    = lane & 3;
    const int warpM = (wid & 1) * 64;
    const int warpN = (wid >> 1) * 32;
    const int gRow = blockIdx.y * 128;

    auto issueA = [&](int k0, int s) {
#pragma unroll
        for (int i = 0; i < 2; i++) {
            int idx = tid + i * 256;
            int m = idx >> 2, kq = (idx & 3) << 2;
            int gm = gRow + m;
            cp16(&As[s * 128 * LDSA + m * LDSA + kq], &A[(size_t)gm * K + k0 + kq], gm < M);
        }
    };
    auto issueB = [&](const float* B, int k0, int s) {
#pragma unroll
        for (int i = 0; i < 2; i++) {
            int idx = tid + i * 256;
            int k = idx >> 5, n4 = (idx & 31) << 2;
            cp16(&Bs[s * BK * LDSN + k * LDSN + n4], &B[(size_t)(k0 + k) * N + n4], true);
        }
    };

    float c[4][4][4];
    auto zeroC = [&]() {
#pragma unroll
        for (int mt = 0; mt < 4; mt++)
#pragma unroll
            for (int nt = 0; nt < 4; nt++)
#pragma unroll
                for (int i = 0; i < 4; i++) c[mt][nt][i] = 0.f;
    };

    // stage 1: H = relu(A @ fc1 + fc1b)
    zeroC();
    issueA(0, 0); issueB(fc1w, 0, 0);
    CP_COMMIT;
    const int T = K / BK;
    for (int it = 0; it < T; it++) {
        int s = it & 1;
        if (it + 1 < T) {
            issueA((it + 1) * BK, s ^ 1); issueB(fc1w, (it + 1) * BK, s ^ 1);
            CP_COMMIT; CP_WAIT(1);
        } else CP_WAIT(0);
        __syncthreads();
#pragma unroll
        for (int kk = 0; kk < BK; kk += 8) {
            uint32_t af[4][4], bf[4][2];
#pragma unroll
            for (int mt = 0; mt < 4; mt++) {
                int m0 = warpM + mt * 16 + g;
                const float* Ab = &As[s * 128 * LDSA];
                af[mt][0] = f2tf32(Ab[(m0    ) * LDSA + kk + t    ]);
                af[mt][1] = f2tf32(Ab[(m0 + 8) * LDSA + kk + t    ]);
                af[mt][2] = f2tf32(Ab[(m0    ) * LDSA + kk + t + 4]);
                af[mt][3] = f2tf32(Ab[(m0 + 8) * LDSA + kk + t + 4]);
            }
#pragma unroll
            for (int nt = 0; nt < 4; nt++) {
                int n0 = warpN + nt * 8 + g;
                const float* Bb = &Bs[s * BK * LDSN];
                bf[nt][0] = f2tf32(Bb[(kk + t    ) * LDSN + n0]);
                bf[nt][1] = f2tf32(Bb[(kk + t + 4) * LDSN + n0]);
            }
#pragma unroll
            for (int mt = 0; mt < 4; mt++)
#pragma unroll
                for (int nt = 0; nt < 4; nt++)
                    mma_tf32(c[mt][nt], af[mt], bf[nt]);
        }
        __syncthreads();
    }
#pragma unroll
    for (int mt = 0; mt < 4; mt++) {
        int m0 = warpM + mt * 16 + g;
#pragma unroll
        for (int nt = 0; nt < 4; nt++) {
            int col = warpN + nt * 8 + t * 2;
            float b0 = fc1b[col], b1 = fc1b[col + 1];
            float v0 = fmaxf(c[mt][nt][0] + b0, 0.f);
            float v1 = fmaxf(c[mt][nt][1] + b1, 0.f);
            float v2 = fmaxf(c[mt][nt][2] + b0, 0.f);
            float v3 = fmaxf(c[mt][nt][3] + b1, 0.f);
            *reinterpret_cast<float2*>(&H[(m0    ) * LDH + col]) = make_float2(v0, v1);
            *reinterpret_cast<float2*>(&H[(m0 + 8) * LDH + col]) = make_float2(v2, v3);
        }
    }
    __syncthreads();

    // stage 2: C = H @ fc2 + fc2b
    zeroC();
    issueB(fc2w, 0, 0);
    CP_COMMIT;
    for (int it = 0; it < T; it++) {
        int s = it & 1;
        if (it + 1 < T) {
            issueB(fc2w, (it + 1) * BK, s ^ 1);
            CP_COMMIT; CP_WAIT(1);
        } else CP_WAIT(0);
        __syncthreads();
        int kbase = it * BK;
#pragma unroll
        for (int kk = 0; kk < BK; kk += 8) {
            uint32_t af[4][4], bf[4][2];
#pragma unroll
            for (int mt = 0; mt < 4; mt++) {
                int m0 = warpM + mt * 16 + g;
                af[mt][0] = f2tf32(H[(m0    ) * LDH + kbase + kk + t    ]);
                af[mt][1] = f2tf32(H[(m0 + 8) * LDH + kbase + kk + t    ]);
                af[mt][2] = f2tf32(H[(m0    ) * LDH + kbase + kk + t + 4]);
                af[mt][3] = f2tf32(H[(m0 + 8) * LDH + kbase + kk + t + 4]);
            }
#pragma unroll
            for (int nt = 0; nt < 4; nt++) {
                int n0 = warpN + nt * 8 + g;
                const float* Bb = &Bs[s * BK * LDSN];
                bf[nt][0] = f2tf32(Bb[(kk + t    ) * LDSN + n0]);
                bf[nt][1] = f2tf32(Bb[(kk + t + 4) * LDSN + n0]);
            }
#pragma unroll
            for (int mt = 0; mt < 4; mt++)
#pragma unroll
                for (int nt = 0; nt < 4; nt++)
                    mma_tf32(c[mt][nt], af[mt], bf[nt]);
        }
        __syncthreads();
    }
#pragma unroll
    for (int mt = 0; mt < 4; mt++) {
        int r0 = gRow + warpM + mt * 16 + g;
        int r1 = r0 + 8;
#pragma unroll
        for (int nt = 0; nt < 4; nt++) {
            int col = warpN + nt * 8 + t * 2;
            float b0 = fc2b[col], b1 = fc2b[col + 1];
            if (r0 < M)
                *reinterpret_cast<float2*>(&C[(size_t)r0 * N + col]) =
                    make_float2(c[mt][nt][0] + b0, c[mt][nt][1] + b1);
            if (r1 < M)
                *reinterpret_cast<float2*>(&C[(size_t)r1 * N + col]) =
                    make_float2(c[mt][nt][2] + b0, c[mt][nt][3] + b1);
        }
    }
}

// ---------------- launch ----------------
extern "C" void kernel_launch(void* const* d_in, const int* in_sizes, int n_in,
                              void* d_out, int out_size) {
    const float* x    = (const float*)d_in[0];
    const int*   ei   = (const int*)d_in[1];
    const float* W1   = (const float*)d_in[2];
    const float* b1   = (const float*)d_in[3];
    const float* W2   = (const float*)d_in[4];
    const float* b2   = (const float*)d_in[5];
    const float* a    = (const float*)d_in[6];
    const float* fc1w = (const float*)d_in[7];
    const float* fc1b = (const float*)d_in[8];
    const float* fc2w = (const float*)d_in[9];
    const float* fc2b = (const float*)d_in[10];

    const int N = in_sizes[0] / 128;      // 100000 nodes
    const int E = in_sizes[1] / 2;        // 1600000 edges
    const int* src = ei;
    const int* dst = ei + E;

    float* out  = (float*)d_out;                    // [N,128]
    float* proj = out + (size_t)N * 128;            // [N,128]

    float *pd, *pagg, *pout1;
    __half* ph16;
    int *pdeg, *pexcl, *pbtot, *prowp, *pcur, *pcsrc;
    cudaGetSymbolAddress((void**)&pd,    g_dinv);
    cudaGetSymbolAddress((void**)&pagg,  g_agg);
    cudaGetSymbolAddress((void**)&pout1, g_out1);
    cudaGetSymbolAddress((void**)&ph16,  g_h16);
    cudaGetSymbolAddress((void**)&pdeg,  g_deg);
    cudaGetSymbolAddress((void**)&pexcl, g_excl);
    cudaGetSymbolAddress((void**)&pbtot, g_btot);
    cudaGetSymbolAddress((void**)&prowp, g_rowp);
    cudaGetSymbolAddress((void**)&pcur,  g_cur);
    cudaGetSymbolAddress((void**)&pcsrc, g_csrc);

    const int TPB = 256;
    const int nb  = (N + SCAN_B - 1) / SCAN_B;
    const int n4  = N * 32;
    const int aggWarps  = (N + 1) / 2;                       // 2 nodes per warp
    const int aggBlocks = (aggWarps * 32 + TPB - 1) / TPB;
    const int projSmem = (2 * 128 * 20 + 2 * 16 * 136 + 128 * 132) * 4;

    cudaFuncSetAttribute(k_proj, cudaFuncAttributeMaxDynamicSharedMemorySize, projSmem);

    // ---- CSR build (dinv needed before prescaled f2h) ----
    k_hist<<<(E + TPB - 1) / TPB, TPB>>>(dst, pdeg, E);
    k_scan_blocks<<<nb, SCAN_B>>>(pdeg, pexcl, pbtot, N);
    k_scan_tops<<<1, 128>>>(pbtot, nb);
    k_finalize<<<(N + TPB - 1) / TPB, TPB>>>(pdeg, pexcl, pbtot, prowp, pcur, pd, N);
    k_f2h_scaled<<<(n4 + TPB - 1) / TPB, TPB>>>(x, pd, ph16, n4);
    k_fillcsr<<<(E + TPB - 1) / TPB, TPB>>>(src, dst, pcur, pcsrc, E);

    // ---- layer 1: agg(prescaled x16) -> fp32 ; GEMM1 ----
    k_agg16<false><<<aggBlocks, TPB>>>(prowp, pcsrc, pd, ph16, pagg,
                                       nullptr, nullptr, nullptr, N);
    dim3 grid1(2, (N + 127) / 128);
    dim3 grid2(1, (N + 127) / 128);
    tgemm128<1><<<grid1, 256>>>(N, 256, 128, pagg, W1, b1, a, nullptr, pout1, nullptr);

    // ---- layer 2: h2 = (out1 @ W2) * dinv stored fp16 ; agg final ----
    tgemm128<5><<<grid2, 256>>>(N, 128, 256, pout1, W2, nullptr, nullptr, pd, nullptr, ph16);
    k_agg16<true><<<aggBlocks, TPB>>>(prowp, pcsrc, pd, ph16, pagg,
                                      b2, a, out, N);

    // ---- fused proj head ----
    k_proj<<<grid2, 256, projSmem>>>(N, pagg, fc1w, fc1b, fc2w, fc2b, proj);
}

// round 15
// speedup vs baseline: 1.2110x; 1.2110x over previous
#include <cuda_runtime.h>
#include <cuda_fp16.h>
#include <cstdint>

// ---------------- static scratch (no allocations allowed) ----------------
#define MAXN 100000
#define MAXE 1600000
#define SCAN_B 1024

__device__ float  g_dinv[MAXN];
__device__ __half g_h16 [MAXN * 128];     // prescaled gather buffer (x, then h2)
__device__ __half g_a16 [MAXN * 128];     // agg1 out ; later final-out fp16 mirror
__device__ __half g_o116[MAXN * 256];     // layer-1 output (fp16)
__device__ __half g_w16 [98304];          // transposed fp16 weights: W1t,W2t,fc1t,fc2t
__device__ int    g_deg [MAXN];           // zero at entry; re-zeroed in k_finalize
__device__ int    g_excl[MAXN];
__device__ int    g_btot[128];
__device__ int    g_rowp[MAXN + 1];
__device__ int    g_cur [MAXN];
__device__ int    g_csrc[MAXE];

// weight segment offsets in g_w16
#define W1T_OFF 0          // [256][128]
#define W2T_OFF 32768      // [128][256]
#define F1T_OFF 65536      // [128][128]
#define F2T_OFF 81920      // [128][128]

// ---------------- weight convert + transpose: fp32 [k][n] -> fp16 [n][k] ----
__global__ void k_wconv(const float* __restrict__ W1, const float* __restrict__ W2,
                        const float* __restrict__ f1, const float* __restrict__ f2,
                        __half* __restrict__ w) {
    int i = blockIdx.x * blockDim.x + threadIdx.x;
    if (i < 32768) {                       // W1 [128][256]
        int k = i >> 8, n = i & 255;
        w[W1T_OFF + n * 128 + k] = __float2half_rn(W1[i]);
    } else if (i < 65536) {                // W2 [256][128]
        int j = i - 32768;
        int k = j >> 7, n = j & 127;
        w[W2T_OFF + n * 256 + k] = __float2half_rn(W2[j]);
    } else if (i < 81920) {                // fc1 [128][128]
        int j = i - 65536;
        int k = j >> 7, n = j & 127;
        w[F1T_OFF + n * 128 + k] = __float2half_rn(f1[j]);
    } else if (i < 98304) {                // fc2 [128][128]
        int j = i - 81920;
        int k = j >> 7, n = j & 127;
        w[F2T_OFF + n * 128 + k] = __float2half_rn(f2[j]);
    }
}

// xh[row] = fp16( x[row] * dinv[row] )
__global__ void k_f2h_scaled(const float* __restrict__ x,
                             const float* __restrict__ dinv,
                             __half* __restrict__ xh, int n4) {
    int i = blockIdx.x * blockDim.x + threadIdx.x;
    if (i >= n4) return;
    float s = dinv[i >> 5];
    float4 v = reinterpret_cast<const float4*>(x)[i];
    __half2 p0 = __floats2half2_rn(v.x * s, v.y * s);
    __half2 p1 = __floats2half2_rn(v.z * s, v.w * s);
    uint2 r;
    r.x = *reinterpret_cast<uint32_t*>(&p0);
    r.y = *reinterpret_cast<uint32_t*>(&p1);
    reinterpret_cast<uint2*>(xh)[i] = r;
}

// ---------------- CSR build ----------------
__global__ void k_hist(const int* __restrict__ dst, int* deg, int E) {
    int e = blockIdx.x * blockDim.x + threadIdx.x;
    if (e < E) atomicAdd(&deg[dst[e]], 1);
}

__global__ void k_scan_blocks(const int* __restrict__ deg, int* excl,
                              int* btot, int n) {
    __shared__ int sh[SCAN_B];
    int t = threadIdx.x;
    int i = blockIdx.x * SCAN_B + t;
    int v = (i < n) ? deg[i] : 0;
    sh[t] = v;
    __syncthreads();
    for (int off = 1; off < SCAN_B; off <<= 1) {
        int add = (t >= off) ? sh[t - off] : 0;
        __syncthreads();
        sh[t] += add;
        __syncthreads();
    }
    if (i < n) excl[i] = sh[t] - v;
    if (t == SCAN_B - 1) btot[blockIdx.x] = sh[t];
}

__global__ void k_scan_tops(int* btot, int nb) {
    __shared__ int sh[128];
    int t = threadIdx.x;
    int v = (t < nb) ? btot[t] : 0;
    sh[t] = v;
    __syncthreads();
    for (int off = 1; off < 128; off <<= 1) {
        int add = (t >= off) ? sh[t - off] : 0;
        __syncthreads();
        sh[t] += add;
        __syncthreads();
    }
    if (t < nb) btot[t] = sh[t] - v;
}

__global__ void k_finalize(int* deg, const int* __restrict__ excl,
                           const int* __restrict__ btot,
                           int* rowp, int* cur, float* dinv, int n) {
    int i = blockIdx.x * blockDim.x + threadIdx.x;
    if (i >= n) return;
    int dg = deg[i];
    int rp = excl[i] + btot[i >> 10];
    rowp[i] = rp;
    cur[i]  = rp;
    dinv[i] = rsqrtf((float)dg + 1.0f);
    if (i == n - 1) rowp[n] = rp + dg;
    deg[i] = 0;
}

__global__ void k_fillcsr(const int* __restrict__ src, const int* __restrict__ dst,
                          int* cur, int* csrc, int E) {
    int e = blockIdx.x * blockDim.x + threadIdx.x;
    if (e >= E) return;
    int pos = atomicAdd(&cur[dst[e]], 1);
    csrc[pos] = src[e];
}

// -------- CSR aggregation (prescaled fp16 rows), warp per dst node --------
// out[d] = dinv[d] * ( p[d] + sum_s p[s] ).
// !FINAL: store fp16 to outh.  FINAL: bias+prelu; fp32 to outf AND fp16 to outh.
template <bool FINAL>
__global__ void k_agg16(const int* __restrict__ rowp, const int* __restrict__ csrc,
                        const float* __restrict__ dinv, const __half* __restrict__ h,
                        __half* __restrict__ outh,
                        const float* __restrict__ bias, const float* __restrict__ ap,
                        float* __restrict__ outf, int n) {
    int gtid = blockIdx.x * blockDim.x + threadIdx.x;
    int d = gtid >> 5, lane = gtid & 31;
    if (d >= n) return;

    float4 acc;
    {
        uint2 r = reinterpret_cast<const uint2*>(h + (size_t)d * 128)[lane];
        __half2 p0 = *reinterpret_cast<__half2*>(&r.x);
        __half2 p1 = *reinterpret_cast<__half2*>(&r.y);
        float2 f0 = __half22float2(p0), f1 = __half22float2(p1);
        acc = make_float4(f0.x, f0.y, f1.x, f1.y);
    }

    int j = rowp[d], end = rowp[d + 1];
    for (; j + 8 <= end; j += 8) {
        int s[8];
#pragma unroll
        for (int u = 0; u < 8; u++) s[u] = csrc[j + u];
        uint2 r[8];
#pragma unroll
        for (int u = 0; u < 8; u++)
            r[u] = reinterpret_cast<const uint2*>(h + (size_t)s[u] * 128)[lane];
#pragma unroll
        for (int u = 0; u < 8; u++) {
            __half2 p0 = *reinterpret_cast<__half2*>(&r[u].x);
            __half2 p1 = *reinterpret_cast<__half2*>(&r[u].y);
            float2 f0 = __half22float2(p0), f1 = __half22float2(p1);
            acc.x += f0.x; acc.y += f0.y; acc.z += f1.x; acc.w += f1.y;
        }
    }
    if (j + 4 <= end) {
        int s[4];
#pragma unroll
        for (int u = 0; u < 4; u++) s[u] = csrc[j + u];
        uint2 r[4];
#pragma unroll
        for (int u = 0; u < 4; u++)
            r[u] = reinterpret_cast<const uint2*>(h + (size_t)s[u] * 128)[lane];
#pragma unroll
        for (int u = 0; u < 4; u++) {
            __half2 p0 = *reinterpret_cast<__half2*>(&r[u].x);
            __half2 p1 = *reinterpret_cast<__half2*>(&r[u].y);
            float2 f0 = __half22float2(p0), f1 = __half22float2(p1);
            acc.x += f0.x; acc.y += f0.y; acc.z += f1.x; acc.w += f1.y;
        }
        j += 4;
    }
    for (; j < end; j++) {
        uint2 r = reinterpret_cast<const uint2*>(h + (size_t)csrc[j] * 128)[lane];
        __half2 p0 = *reinterpret_cast<__half2*>(&r.x);
        __half2 p1 = *reinterpret_cast<__half2*>(&r.y);
        float2 f0 = __half22float2(p0), f1 = __half22float2(p1);
        acc.x += f0.x; acc.y += f0.y; acc.z += f1.x; acc.w += f1.y;
    }

    float dd = dinv[d];
    acc.x *= dd; acc.y *= dd; acc.z *= dd; acc.w *= dd;

    if (FINAL) {
        float a = *ap;
        float4 bb = reinterpret_cast<const float4*>(bias)[lane];
        acc.x += bb.x; acc.y += bb.y; acc.z += bb.z; acc.w += bb.w;
        acc.x = acc.x >= 0.f ? acc.x : a * acc.x;
        acc.y = acc.y >= 0.f ? acc.y : a * acc.y;
        acc.z = acc.z >= 0.f ? acc.z : a * acc.z;
        acc.w = acc.w >= 0.f ? acc.w : a * acc.w;
        reinterpret_cast<float4*>(outf + (size_t)d * 128)[lane] = acc;
    }
    __half2 q0 = __floats2half2_rn(acc.x, acc.y);
    __half2 q1 = __floats2half2_rn(acc.z, acc.w);
    uint2 o;
    o.x = *reinterpret_cast<uint32_t*>(&q0);
    o.y = *reinterpret_cast<uint32_t*>(&q1);
    reinterpret_cast<uint2*>(outh + (size_t)d * 128)[lane] = o;
}

// ------------- fp16 tensor-core GEMM (m16n8k16), cp.async 2-stage -------------
__device__ __forceinline__ void mma_f16(float* c, const uint32_t* a, const uint32_t* b) {
    asm volatile(
        "mma.sync.aligned.m16n8k16.row.col.f32.f16.f16.f32 "
        "{%0,%1,%2,%3}, {%4,%5,%6,%7}, {%8,%9}, {%0,%1,%2,%3};"
        : "+f"(c[0]), "+f"(c[1]), "+f"(c[2]), "+f"(c[3])
        : "r"(a[0]), "r"(a[1]), "r"(a[2]), "r"(a[3]),
          "r"(b[0]), "r"(b[1]));
}

__device__ __forceinline__ void cp16(void* smem_dst, const void* gsrc, bool valid) {
    uint32_t saddr = (uint32_t)__cvta_generic_to_shared(smem_dst);
    int sz = valid ? 16 : 0;
    asm volatile("cp.async.cg.shared.global [%0], [%1], 16, %2;"
                 :: "r"(saddr), "l"(gsrc), "r"(sz));
}
#define CP_COMMIT asm volatile("cp.async.commit_group;")
#define CP_WAIT(n) asm volatile("cp.async.wait_group %0;" :: "n"(n))

__device__ __forceinline__ uint32_t lds32h(const __half* p) {
    return *reinterpret_cast<const uint32_t*>(p);
}

// A: [M][K] fp16 row-major. Bt: [N][K] fp16 (pre-transposed).
// EPI 1: fp16(prelu(acc+bias)) -> Ch.   EPI 5: fp16(acc*dinv[row]) -> Ch.
template <int EPI>
__global__ __launch_bounds__(256) void tgemm16(
    int M, int N, int K,
    const __half* __restrict__ A, const __half* __restrict__ Bt,
    const float* __restrict__ bias, const float* __restrict__ prelu_a,
    const float* __restrict__ dinvp,
    __half* __restrict__ Ch)
{
    constexpr int BK = 32;       // halfs per tile
    constexpr int LDS = 40;      // padded stride (halfs); banks 20g+t all distinct
    __shared__ __half As[2][128 * LDS];
    __shared__ __half Bs[2][128 * LDS];

    const int tid  = threadIdx.x;
    const int lane = tid & 31;
    const int wid  = tid >> 5;
    const int g    = lane >> 2;
    const int t    = lane & 3;

    const int warpM = (wid & 1) * 64;
    const int warpN = (wid >> 1) * 32;

    const int gRow = blockIdx.y * 128;
    const int gCol = blockIdx.x * 128;

    auto issueTile = [&](int k0, int s) {
#pragma unroll
        for (int i = 0; i < 2; i++) {
            int idx = tid + i * 256;
            int m  = idx >> 2, kq = (idx & 3) << 3;       // 8 halfs = 16B
            int gm = gRow + m;
            cp16(&As[s][m * LDS + kq], &A[(size_t)gm * K + k0 + kq], gm < M);
        }
#pragma unroll
        for (int i = 0; i < 2; i++) {
            int idx = tid + i * 256;
            int nn = idx >> 2, kq = (idx & 3) << 3;
            cp16(&Bs[s][nn * LDS + kq], &Bt[(size_t)(gCol + nn) * K + k0 + kq], true);
        }
    };

    float c[4][4][4];
#pragma unroll
    for (int mt = 0; mt < 4; mt++)
#pragma unroll
        for (int nt = 0; nt < 4; nt++)
#pragma unroll
            for (int i = 0; i < 4; i++) c[mt][nt][i] = 0.f;

    const int T = K / BK;
    issueTile(0, 0);
    CP_COMMIT;

    for (int it = 0; it < T; it++) {
        int s = it & 1;
        if (it + 1 < T) {
            issueTile((it + 1) * BK, s ^ 1);
            CP_COMMIT;
            CP_WAIT(1);
        } else {
            CP_WAIT(0);
        }
        __syncthreads();

#pragma unroll
        for (int kk = 0; kk < BK; kk += 16) {
            uint32_t af[4][4], bf[4][2];
#pragma unroll
            for (int mt = 0; mt < 4; mt++) {
                int m0 = warpM + mt * 16 + g;
                const __half* Ab = &As[s][0];
                af[mt][0] = lds32h(&Ab[(m0    ) * LDS + kk + 2 * t    ]);
                af[mt][1] = lds32h(&Ab[(m0 + 8) * LDS + kk + 2 * t    ]);
                af[mt][2] = lds32h(&Ab[(m0    ) * LDS + kk + 2 * t + 8]);
                af[mt][3] = lds32h(&Ab[(m0 + 8) * LDS + kk + 2 * t + 8]);
            }
#pragma unroll
            for (int nt = 0; nt < 4; nt++) {
                int n0 = warpN + nt * 8 + g;
                const __half* Bb = &Bs[s][0];
                bf[nt][0] = lds32h(&Bb[n0 * LDS + kk + 2 * t    ]);
                bf[nt][1] = lds32h(&Bb[n0 * LDS + kk + 2 * t + 8]);
            }
#pragma unroll
            for (int mt = 0; mt < 4; mt++)
#pragma unroll
                for (int nt = 0; nt < 4; nt++)
                    mma_f16(c[mt][nt], af[mt], bf[nt]);
        }
        __syncthreads();
    }

    float a_val = 0.f;
    if (EPI == 1) a_val = *prelu_a;

#pragma unroll
    for (int mt = 0; mt < 4; mt++) {
        int r0 = gRow + warpM + mt * 16 + g;
        int r1 = r0 + 8;
        float s0 = 1.f, s1 = 1.f;
        if (EPI == 5) {
            if (r0 < M) s0 = dinvp[r0];
            if (r1 < M) s1 = dinvp[r1];
        }
#pragma unroll
        for (int nt = 0; nt < 4; nt++) {
            int col = gCol + warpN + nt * 8 + t * 2;
            float v0 = c[mt][nt][0], v1 = c[mt][nt][1];
            float v2 = c[mt][nt][2], v3 = c[mt][nt][3];

            if (EPI == 1) {
                float b0 = bias[col], b1 = bias[col + 1];
                v0 += b0; v1 += b1; v2 += b0; v3 += b1;
                v0 = v0 >= 0.f ? v0 : a_val * v0;
                v1 = v1 >= 0.f ? v1 : a_val * v1;
                v2 = v2 >= 0.f ? v2 : a_val * v2;
                v3 = v3 >= 0.f ? v3 : a_val * v3;
            }
            if (EPI == 5) { v0 *= s0; v1 *= s0; v2 *= s1; v3 *= s1; }

            if (r0 < M)
                *reinterpret_cast<__half2*>(&Ch[(size_t)r0 * N + col]) =
                    __floats2half2_rn(v0, v1);
            if (r1 < M)
                *reinterpret_cast<__half2*>(&Ch[(size_t)r1 * N + col]) =
                    __floats2half2_rn(v2, v3);
        }
    }
}

// ---- fused proj head (fp16): proj = relu(A@fc1+b1)@fc2 + b2, H in smem ----
__global__ __launch_bounds__(256) void k_proj16(
    int M,
    const __half* __restrict__ A,          // [M][128] fp16
    const __half* __restrict__ f1t,        // [128][128] fp16 (n-major)
    const float* __restrict__ fc1b,
    const __half* __restrict__ f2t,        // [128][128] fp16
    const float* __restrict__ fc2b,
    float* __restrict__ C)
{
    constexpr int BK = 32, LDS = 40, LDH = 136, K = 128, N = 128;
    extern __shared__ __half sm[];
    __half* As = sm;                       // 2 * 128*40
    __half* Bs = As + 2 * 128 * LDS;       // 2 * 128*40
    __half* H  = Bs + 2 * 128 * LDS;       // 128*136

    const int tid  = threadIdx.x;
    const int lane = tid & 31;
    const int wid  = tid >> 5;
    const int g    = lane >> 2;
    const int t    = lane & 3;
    const int warpM = (wid & 1) * 64;
    const int warpN = (wid >> 1) * 32;
    const int gRow = blockIdx.y * 128;

    auto issueA = [&](int k0, int s) {
#pragma unroll
        for (int i = 0; i < 2; i++) {
            int idx = tid + i * 256;
            int m = idx >> 2, kq = (idx & 3) << 3;
            int gm = gRow + m;
            cp16(&As[s * 128 * LDS + m * LDS + kq], &A[(size_t)gm * K + k0 + kq], gm < M);
        }
    };
    auto issueB = [&](const __half* Bt, int k0, int s) {
#pragma unroll
        for (int i = 0; i < 2; i++) {
            int idx = tid + i * 256;
            int nn = idx >> 2, kq = (idx & 3) << 3;
            cp16(&Bs[s * 128 * LDS + nn * LDS + kq], &Bt[(size_t)nn * K + k0 + kq], true);
        }
    };

    float c[4][4][4];
    auto zeroC = [&]() {
#pragma unroll
        for (int mt = 0; mt < 4; mt++)
#pragma unroll
            for (int nt = 0; nt < 4; nt++)
#pragma unroll
                for (int i = 0; i < 4; i++) c[mt][nt][i] = 0.f;
    };

    const int T = K / BK;

    // ---------- stage 1: H = relu(A @ fc1 + fc1b) ----------
    zeroC();
    issueA(0, 0); issueB(f1t, 0, 0);
    CP_COMMIT;
    for (int it = 0; it < T; it++) {
        int s = it & 1;
        if (it + 1 < T) {
            issueA((it + 1) * BK, s ^ 1); issueB(f1t, (it + 1) * BK, s ^ 1);
            CP_COMMIT; CP_WAIT(1);
        } else CP_WAIT(0);
        __syncthreads();
#pragma unroll
        for (int kk = 0; kk < BK; kk += 16) {
            uint32_t af[4][4], bf[4][2];
#pragma unroll
            for (int mt = 0; mt < 4; mt++) {
                int m0 = warpM + mt * 16 + g;
                const __half* Ab = &As[s * 128 * LDS];
                af[mt][0] = lds32h(&Ab[(m0    ) * LDS + kk + 2 * t    ]);
                af[mt][1] = lds32h(&Ab[(m0 + 8) * LDS + kk + 2 * t    ]);
                af[mt][2] = lds32h(&Ab[(m0    ) * LDS + kk + 2 * t + 8]);
                af[mt][3] = lds32h(&Ab[(m0 + 8) * LDS + kk + 2 * t + 8]);
            }
#pragma unroll
            for (int nt = 0; nt < 4; nt++) {
                int n0 = warpN + nt * 8 + g;
                const __half* Bb = &Bs[s * 128 * LDS];
                bf[nt][0] = lds32h(&Bb[n0 * LDS + kk + 2 * t    ]);
                bf[nt][1] = lds32h(&Bb[n0 * LDS + kk + 2 * t + 8]);
            }
#pragma unroll
            for (int mt = 0; mt < 4; mt++)
#pragma unroll
                for (int nt = 0; nt < 4; nt++)
                    mma_f16(c[mt][nt], af[mt], bf[nt]);
        }
        __syncthreads();
    }
    // relu + bias -> H fp16, [m][k] stride LDH (banks 68g+t ≡ 4g+t: distinct)
#pragma unroll
    for (int mt = 0; mt < 4; mt++) {
        int m0 = warpM + mt * 16 + g;
#pragma unroll
        for (int nt = 0; nt < 4; nt++) {
            int col = warpN + nt * 8 + t * 2;
            float b0 = fc1b[col], b1 = fc1b[col + 1];
            float v0 = fmaxf(c[mt][nt][0] + b0, 0.f);
            float v1 = fmaxf(c[mt][nt][1] + b1, 0.f);
            float v2 = fmaxf(c[mt][nt][2] + b0, 0.f);
            float v3 = fmaxf(c[mt][nt][3] + b1, 0.f);
            *reinterpret_cast<__half2*>(&H[(m0    ) * LDH + col]) = __floats2half2_rn(v0, v1);
            *reinterpret_cast<__half2*>(&H[(m0 + 8) * LDH + col]) = __floats2half2_rn(v2, v3);
        }
    }
    __syncthreads();

    // ---------- stage 2: C = H @ fc2 + fc2b ----------
    zeroC();
    issueB(f2t, 0, 0);
    CP_COMMIT;
    for (int it = 0; it < T; it++) {
        int s = it & 1;
        if (it + 1 < T) {
            issueB(f2t, (it + 1) * BK, s ^ 1);
            CP_COMMIT; CP_WAIT(1);
        } else CP_WAIT(0);
        __syncthreads();
        int kbase = it * BK;
#pragma unroll
        for (int kk = 0; kk < BK; kk += 16) {
            uint32_t af[4][4], bf[4][2];
#pragma unroll
            for (int mt = 0; mt < 4; mt++) {
                int m0 = warpM + mt * 16 + g;
                af[mt][0] = lds32h(&H[(m0    ) * LDH + kbase + kk + 2 * t    ]);
                af[mt][1] = lds32h(&H[(m0 + 8) * LDH + kbase + kk + 2 * t    ]);
                af[mt][2] = lds32h(&H[(m0    ) * LDH + kbase + kk + 2 * t + 8]);
                af[mt][3] = lds32h(&H[(m0 + 8) * LDH + kbase + kk + 2 * t + 8]);
            }
#pragma unroll
            for (int nt = 0; nt < 4; nt++) {
                int n0 = warpN + nt * 8 + g;
                const __half* Bb = &Bs[s * 128 * LDS];
                bf[nt][0] = lds32h(&Bb[n0 * LDS + kk + 2 * t    ]);
                bf[nt][1] = lds32h(&Bb[n0 * LDS + kk + 2 * t + 8]);
            }
#pragma unroll
            for (int mt = 0; mt < 4; mt++)
#pragma unroll
                for (int nt = 0; nt < 4; nt++)
                    mma_f16(c[mt][nt], af[mt], bf[nt]);
        }
        __syncthreads();
    }
#pragma unroll
    for (int mt = 0; mt < 4; mt++) {
        int r0 = gRow + warpM + mt * 16 + g;
        int r1 = r0 + 8;
#pragma unroll
        for (int nt = 0; nt < 4; nt++) {
            int col = warpN + nt * 8 + t * 2;
            float b0 = fc2b[col], b1 = fc2b[col + 1];
            if (r0 < M)
                *reinterpret_cast<float2*>(&C[(size_t)r0 * N + col]) =
                    make_float2(c[mt][nt][0] + b0, c[mt][nt][1] + b1);
            if (r1 < M)
                *reinterpret_cast<float2*>(&C[(size_t)r1 * N + col]) =
                    make_float2(c[mt][nt][2] + b0, c[mt][nt][3] + b1);
        }
    }
}

// ---------------- launch ----------------
extern "C" void kernel_launch(void* const* d_in, const int* in_sizes, int n_in,
                              void* d_out, int out_size) {
    const float* x    = (const float*)d_in[0];
    const int*   ei   = (const int*)d_in[1];
    const float* W1   = (const float*)d_in[2];
    const float* b1   = (const float*)d_in[3];
    const float* W2   = (const float*)d_in[4];
    const float* b2   = (const float*)d_in[5];
    const float* a    = (const float*)d_in[6];
    const float* fc1w = (const float*)d_in[7];
    const float* fc1b = (const float*)d_in[8];
    const float* fc2w = (const float*)d_in[9];
    const float* fc2b = (const float*)d_in[10];

    const int N = in_sizes[0] / 128;      // 100000 nodes
    const int E = in_sizes[1] / 2;        // 1600000 edges
    const int* src = ei;
    const int* dst = ei + E;

    float* out  = (float*)d_out;                    // [N,128]
    float* proj = out + (size_t)N * 128;            // [N,128]

    float* pd;
    __half *ph16, *pa16, *po116, *pw16;
    int *pdeg, *pexcl, *pbtot, *prowp, *pcur, *pcsrc;
    cudaGetSymbolAddress((void**)&pd,    g_dinv);
    cudaGetSymbolAddress((void**)&ph16,  g_h16);
    cudaGetSymbolAddress((void**)&pa16,  g_a16);
    cudaGetSymbolAddress((void**)&po116, g_o116);
    cudaGetSymbolAddress((void**)&pw16,  g_w16);
    cudaGetSymbolAddress((void**)&pdeg,  g_deg);
    cudaGetSymbolAddress((void**)&pexcl, g_excl);
    cudaGetSymbolAddress((void**)&pbtot, g_btot);
    cudaGetSymbolAddress((void**)&prowp, g_rowp);
    cudaGetSymbolAddress((void**)&pcur,  g_cur);
    cudaGetSymbolAddress((void**)&pcsrc, g_csrc);

    const int TPB = 256;
    const int nb  = (N + SCAN_B - 1) / SCAN_B;
    const int n4  = N * 32;
    const int aggBlocks = (N * 32 + TPB - 1) / TPB;
    const int projSmem = (2 * 128 * 40 * 2 + 128 * 136) * 2;   // halfs * 2B

    cudaFuncSetAttribute(k_proj16, cudaFuncAttributeMaxDynamicSharedMemorySize, projSmem);

    // ---- weights -> fp16 transposed ; CSR build ; x -> prescaled fp16 ----
    k_wconv<<<(98304 + TPB - 1) / TPB, TPB>>>(W1, W2, fc1w, fc2w, pw16);
    k_hist<<<(E + TPB - 1) / TPB, TPB>>>(dst, pdeg, E);
    k_scan_blocks<<<nb, SCAN_B>>>(pdeg, pexcl, pbtot, N);
    k_scan_tops<<<1, 128>>>(pbtot, nb);
    k_finalize<<<(N + TPB - 1) / TPB, TPB>>>(pdeg, pexcl, pbtot, prowp, pcur, pd, N);
    k_f2h_scaled<<<(n4 + TPB - 1) / TPB, TPB>>>(x, pd, ph16, n4);
    k_fillcsr<<<(E + TPB - 1) / TPB, TPB>>>(src, dst, pcur, pcsrc, E);

    dim3 grid1(2, (N + 127) / 128);    // 256 output cols
    dim3 grid2(1, (N + 127) / 128);    // 128 output cols

    // ---- layer 1: agg -> fp16 ; out1 = prelu(agg @ W1 + b1) fp16 ----
    k_agg16<false><<<aggBlocks, TPB>>>(prowp, pcsrc, pd, ph16, pa16,
                                       nullptr, nullptr, nullptr, N);
    tgemm16<1><<<grid1, 256>>>(N, 256, 128, pa16, pw16 + W1T_OFF, b1, a, nullptr, po116);

    // ---- layer 2: h2 = (out1 @ W2) * dinv -> fp16 ; agg final ----
    tgemm16<5><<<grid2, 256>>>(N, 128, 256, po116, pw16 + W2T_OFF, nullptr, nullptr, pd, ph16);
    k_agg16<true><<<aggBlocks, TPB>>>(prowp, pcsrc, pd, ph16, pa16,
                                      b2, a, out, N);

    // ---- fused proj head (fp16 inputs, fp32 out) ----
    k_proj16<<<grid2, 256, projSmem>>>(N, pa16, pw16 + F1T_OFF, fc1b,
                                       pw16 + F2T_OFF, fc2b, proj);
}

// round 16
// speedup vs baseline: 1.2168x; 1.0048x over previous
#include <cuda_runtime.h>
#include <cuda_fp16.h>
#include <cstdint>

// ---------------- static scratch (no allocations allowed) ----------------
#define MAXN 100000
#define MAXE 1600000
#define SCAN_B 1024

__device__ float  g_dinv[MAXN];
__device__ __half g_h16 [MAXN * 128];     // prescaled gather buffer (x, then h2)
__device__ __half g_a16 [MAXN * 128];     // agg1 out ; later final-out fp16 mirror
__device__ __half g_o116[MAXN * 256];     // layer-1 output (fp16)
__device__ __half g_w16 [98304];          // transposed fp16 weights
__device__ int    g_deg [MAXN];           // zero at entry; re-zeroed in k_finalize
__device__ int    g_excl[MAXN];
__device__ int    g_btot[128];
__device__ int    g_rowp[MAXN + 1];
__device__ int    g_cur [MAXN];
__device__ int    g_csrc[MAXE];

#define W1T_OFF 0          // [256][128]
#define W2T_OFF 32768      // [128][256]
#define F1T_OFF 65536      // [128][128]
#define F2T_OFF 81920      // [128][128]

// ---- histogram + (first 98304 threads) weight convert/transpose ----
__global__ void k_hist_wconv(const int* __restrict__ dst, int* deg, int E,
                             const float* __restrict__ W1, const float* __restrict__ W2,
                             const float* __restrict__ f1, const float* __restrict__ f2,
                             __half* __restrict__ w) {
    int i = blockIdx.x * blockDim.x + threadIdx.x;
    if (i < E) atomicAdd(&deg[dst[i]], 1);
    if (i < 32768) {                       // W1 [128][256]
        int k = i >> 8, n = i & 255;
        w[W1T_OFF + n * 128 + k] = __float2half_rn(W1[i]);
    } else if (i < 65536) {                // W2 [256][128]
        int j = i - 32768;
        int k = j >> 7, n = j & 127;
        w[W2T_OFF + n * 256 + k] = __float2half_rn(W2[j]);
    } else if (i < 81920) {                // fc1 [128][128]
        int j = i - 65536;
        int k = j >> 7, n = j & 127;
        w[F1T_OFF + n * 128 + k] = __float2half_rn(f1[j]);
    } else if (i < 98304) {                // fc2 [128][128]
        int j = i - 81920;
        int k = j >> 7, n = j & 127;
        w[F2T_OFF + n * 128 + k] = __float2half_rn(f2[j]);
    }
}

__global__ void k_scan_blocks(const int* __restrict__ deg, int* excl,
                              int* btot, int n) {
    __shared__ int sh[SCAN_B];
    int t = threadIdx.x;
    int i = blockIdx.x * SCAN_B + t;
    int v = (i < n) ? deg[i] : 0;
    sh[t] = v;
    __syncthreads();
    for (int off = 1; off < SCAN_B; off <<= 1) {
        int add = (t >= off) ? sh[t - off] : 0;
        __syncthreads();
        sh[t] += add;
        __syncthreads();
    }
    if (i < n) excl[i] = sh[t] - v;
    if (t == SCAN_B - 1) btot[blockIdx.x] = sh[t];
}

// ---- fused finalize: rowp/cur/dinv/deg-reset + prescaled f2h, warp/node ----
// Block = 256 thr = 8 warps = 8 nodes. Per-block btot prefix computed in smem
// (all 8 nodes share one scan-block: 8 | 1024).
__global__ void k_finalize_f2h(int* deg, const int* __restrict__ excl,
                               const int* __restrict__ btot,
                               int* rowp, int* cur, float* dinv,
                               const float* __restrict__ x, __half* __restrict__ xh,
                               int n, int nb) {
    __shared__ int red[128];
    __shared__ int sOff;
    int t = threadIdx.x;
    int need = (blockIdx.x * 8) >> 10;      // scan-block index of this block's nodes
    if (t < 128) red[t] = (t < need && t < nb) ? btot[t] : 0;
    __syncthreads();
    for (int off = 64; off > 0; off >>= 1) {
        if (t < off) red[t] += red[t + off];
        __syncthreads();
    }
    if (t == 0) sOff = red[0];
    __syncthreads();

    int w = t >> 5, lane = t & 31;
    int d = blockIdx.x * 8 + w;
    if (d >= n) return;

    float di = 0.f;
    if (lane == 0) {
        int dg = deg[d];
        int rp = excl[d] + sOff;
        rowp[d] = rp;
        cur[d]  = rp;
        di = rsqrtf((float)dg + 1.0f);
        dinv[d] = di;
        if (d == n - 1) rowp[n] = rp + dg;
        deg[d] = 0;
    }
    di = __shfl_sync(0xffffffffu, di, 0);

    // f2h: row d, lane handles 4 floats
    float4 v = reinterpret_cast<const float4*>(x + (size_t)d * 128)[lane];
    __half2 p0 = __floats2half2_rn(v.x * di, v.y * di);
    __half2 p1 = __floats2half2_rn(v.z * di, v.w * di);
    uint2 r;
    r.x = *reinterpret_cast<uint32_t*>(&p0);
    r.y = *reinterpret_cast<uint32_t*>(&p1);
    reinterpret_cast<uint2*>(xh + (size_t)d * 128)[lane] = r;
}

__global__ void k_fillcsr(const int* __restrict__ src, const int* __restrict__ dst,
                          int* cur, int* csrc, int E) {
    int e = blockIdx.x * blockDim.x + threadIdx.x;
    if (e >= E) return;
    int pos = atomicAdd(&cur[dst[e]], 1);
    csrc[pos] = src[e];
}

// -------- CSR aggregation (prescaled fp16 rows), warp per dst node --------
template <bool FINAL>
__global__ void k_agg16(const int* __restrict__ rowp, const int* __restrict__ csrc,
                        const float* __restrict__ dinv, const __half* __restrict__ h,
                        __half* __restrict__ outh,
                        const float* __restrict__ bias, const float* __restrict__ ap,
                        float* __restrict__ outf, int n) {
    int gtid = blockIdx.x * blockDim.x + threadIdx.x;
    int d = gtid >> 5, lane = gtid & 31;
    if (d >= n) return;

    float4 acc;
    {
        uint2 r = reinterpret_cast<const uint2*>(h + (size_t)d * 128)[lane];
        __half2 p0 = *reinterpret_cast<__half2*>(&r.x);
        __half2 p1 = *reinterpret_cast<__half2*>(&r.y);
        float2 f0 = __half22float2(p0), f1 = __half22float2(p1);
        acc = make_float4(f0.x, f0.y, f1.x, f1.y);
    }

    int j = rowp[d], end = rowp[d + 1];
    for (; j + 8 <= end; j += 8) {
        int s[8];
#pragma unroll
        for (int u = 0; u < 8; u++) s[u] = csrc[j + u];
        uint2 r[8];
#pragma unroll
        for (int u = 0; u < 8; u++)
            r[u] = reinterpret_cast<const uint2*>(h + (size_t)s[u] * 128)[lane];
#pragma unroll
        for (int u = 0; u < 8; u++) {
            __half2 p0 = *reinterpret_cast<__half2*>(&r[u].x);
            __half2 p1 = *reinterpret_cast<__half2*>(&r[u].y);
            float2 f0 = __half22float2(p0), f1 = __half22float2(p1);
            acc.x += f0.x; acc.y += f0.y; acc.z += f1.x; acc.w += f1.y;
        }
    }
    if (j + 4 <= end) {
        int s[4];
#pragma unroll
        for (int u = 0; u < 4; u++) s[u] = csrc[j + u];
        uint2 r[4];
#pragma unroll
        for (int u = 0; u < 4; u++)
            r[u] = reinterpret_cast<const uint2*>(h + (size_t)s[u] * 128)[lane];
#pragma unroll
        for (int u = 0; u < 4; u++) {
            __half2 p0 = *reinterpret_cast<__half2*>(&r[u].x);
            __half2 p1 = *reinterpret_cast<__half2*>(&r[u].y);
            float2 f0 = __half22float2(p0), f1 = __half22float2(p1);
            acc.x += f0.x; acc.y += f0.y; acc.z += f1.x; acc.w += f1.y;
        }
        j += 4;
    }
    for (; j < end; j++) {
        uint2 r = reinterpret_cast<const uint2*>(h + (size_t)csrc[j] * 128)[lane];
        __half2 p0 = *reinterpret_cast<__half2*>(&r.x);
        __half2 p1 = *reinterpret_cast<__half2*>(&r.y);
        float2 f0 = __half22float2(p0), f1 = __half22float2(p1);
        acc.x += f0.x; acc.y += f0.y; acc.z += f1.x; acc.w += f1.y;
    }

    float dd = dinv[d];
    acc.x *= dd; acc.y *= dd; acc.z *= dd; acc.w *= dd;

    if (FINAL) {
        float a = *ap;
        float4 bb = reinterpret_cast<const float4*>(bias)[lane];
        acc.x += bb.x; acc.y += bb.y; acc.z += bb.z; acc.w += bb.w;
        acc.x = acc.x >= 0.f ? acc.x : a * acc.x;
        acc.y = acc.y >= 0.f ? acc.y : a * acc.y;
        acc.z = acc.z >= 0.f ? acc.z : a * acc.z;
        acc.w = acc.w >= 0.f ? acc.w : a * acc.w;
        reinterpret_cast<float4*>(outf + (size_t)d * 128)[lane] = acc;
    }
    __half2 q0 = __floats2half2_rn(acc.x, acc.y);
    __half2 q1 = __floats2half2_rn(acc.z, acc.w);
    uint2 o;
    o.x = *reinterpret_cast<uint32_t*>(&q0);
    o.y = *reinterpret_cast<uint32_t*>(&q1);
    reinterpret_cast<uint2*>(outh + (size_t)d * 128)[lane] = o;
}

// ------------- fp16 tensor-core GEMM (m16n8k16), cp.async 2-stage -------------
__device__ __forceinline__ void mma_f16(float* c, const uint32_t* a, const uint32_t* b) {
    asm volatile(
        "mma.sync.aligned.m16n8k16.row.col.f32.f16.f16.f32 "
        "{%0,%1,%2,%3}, {%4,%5,%6,%7}, {%8,%9}, {%0,%1,%2,%3};"
        : "+f"(c[0]), "+f"(c[1]), "+f"(c[2]), "+f"(c[3])
        : "r"(a[0]), "r"(a[1]), "r"(a[2]), "r"(a[3]),
          "r"(b[0]), "r"(b[1]));
}

__device__ __forceinline__ void cp16(void* smem_dst, const void* gsrc, bool valid) {
    uint32_t saddr = (uint32_t)__cvta_generic_to_shared(smem_dst);
    int sz = valid ? 16 : 0;
    asm volatile("cp.async.cg.shared.global [%0], [%1], 16, %2;"
                 :: "r"(saddr), "l"(gsrc), "r"(sz));
}
#define CP_COMMIT asm volatile("cp.async.commit_group;")
#define CP_WAIT(n) asm volatile("cp.async.wait_group %0;" :: "n"(n))

__device__ __forceinline__ uint32_t lds32h(const __half* p) {
    return *reinterpret_cast<const uint32_t*>(p);
}

// A: [M][K] fp16 row-major. Bt: [N][K] fp16 (pre-transposed).
// EPI 1: fp16(prelu(acc+bias)) -> Ch.   EPI 5: fp16(acc*dinv[row]) -> Ch.
template <int EPI>
__global__ __launch_bounds__(256) void tgemm16(
    int M, int N, int K,
    const __half* __restrict__ A, const __half* __restrict__ Bt,
    const float* __restrict__ bias, const float* __restrict__ prelu_a,
    const float* __restrict__ dinvp,
    __half* __restrict__ Ch)
{
    constexpr int BK = 32;
    constexpr int LDS = 40;
    __shared__ __half As[2][128 * LDS];
    __shared__ __half Bs[2][128 * LDS];

    const int tid  = threadIdx.x;
    const int lane = tid & 31;
    const int wid  = tid >> 5;
    const int g    = lane >> 2;
    const int t    = lane & 3;

    const int warpM = (wid & 1) * 64;
    const int warpN = (wid >> 1) * 32;

    const int gRow = blockIdx.y * 128;
    const int gCol = blockIdx.x * 128;

    auto issueTile = [&](int k0, int s) {
#pragma unroll
        for (int i = 0; i < 2; i++) {
            int idx = tid + i * 256;
            int m  = idx >> 2, kq = (idx & 3) << 3;
            int gm = gRow + m;
            cp16(&As[s][m * LDS + kq], &A[(size_t)gm * K + k0 + kq], gm < M);
        }
#pragma unroll
        for (int i = 0; i < 2; i++) {
            int idx = tid + i * 256;
            int nn = idx >> 2, kq = (idx & 3) << 3;
            cp16(&Bs[s][nn * LDS + kq], &Bt[(size_t)(gCol + nn) * K + k0 + kq], true);
        }
    };

    float c[4][4][4];
#pragma unroll
    for (int mt = 0; mt < 4; mt++)
#pragma unroll
        for (int nt = 0; nt < 4; nt++)
#pragma unroll
            for (int i = 0; i < 4; i++) c[mt][nt][i] = 0.f;

    const int T = K / BK;
    issueTile(0, 0);
    CP_COMMIT;

    for (int it = 0; it < T; it++) {
        int s = it & 1;
        if (it + 1 < T) {
            issueTile((it + 1) * BK, s ^ 1);
            CP_COMMIT;
            CP_WAIT(1);
        } else {
            CP_WAIT(0);
        }
        __syncthreads();

#pragma unroll
        for (int kk = 0; kk < BK; kk += 16) {
            uint32_t af[4][4], bf[4][2];
#pragma unroll
            for (int mt = 0; mt < 4; mt++) {
                int m0 = warpM + mt * 16 + g;
                const __half* Ab = &As[s][0];
                af[mt][0] = lds32h(&Ab[(m0    ) * LDS + kk + 2 * t    ]);
                af[mt][1] = lds32h(&Ab[(m0 + 8) * LDS + kk + 2 * t    ]);
                af[mt][2] = lds32h(&Ab[(m0    ) * LDS + kk + 2 * t + 8]);
                af[mt][3] = lds32h(&Ab[(m0 + 8) * LDS + kk + 2 * t + 8]);
            }
#pragma unroll
            for (int nt = 0; nt < 4; nt++) {
                int n0 = warpN + nt * 8 + g;
                const __half* Bb = &Bs[s][0];
                bf[nt][0] = lds32h(&Bb[n0 * LDS + kk + 2 * t    ]);
                bf[nt][1] = lds32h(&Bb[n0 * LDS + kk + 2 * t + 8]);
            }
#pragma unroll
            for (int mt = 0; mt < 4; mt++)
#pragma unroll
                for (int nt = 0; nt < 4; nt++)
                    mma_f16(c[mt][nt], af[mt], bf[nt]);
        }
        __syncthreads();
    }

    float a_val = 0.f;
    if (EPI == 1) a_val = *prelu_a;

#pragma unroll
    for (int mt = 0; mt < 4; mt++) {
        int r0 = gRow + warpM + mt * 16 + g;
        int r1 = r0 + 8;
        float s0 = 1.f, s1 = 1.f;
        if (EPI == 5) {
            if (r0 < M) s0 = dinvp[r0];
            if (r1 < M) s1 = dinvp[r1];
        }
#pragma unroll
        for (int nt = 0; nt < 4; nt++) {
            int col = gCol + warpN + nt * 8 + t * 2;
            float v0 = c[mt][nt][0], v1 = c[mt][nt][1];
            float v2 = c[mt][nt][2], v3 = c[mt][nt][3];

            if (EPI == 1) {
                float b0 = bias[col], b1 = bias[col + 1];
                v0 += b0; v1 += b1; v2 += b0; v3 += b1;
                v0 = v0 >= 0.f ? v0 : a_val * v0;
                v1 = v1 >= 0.f ? v1 : a_val * v1;
                v2 = v2 >= 0.f ? v2 : a_val * v2;
                v3 = v3 >= 0.f ? v3 : a_val * v3;
            }
            if (EPI == 5) { v0 *= s0; v1 *= s0; v2 *= s1; v3 *= s1; }

            if (r0 < M)
                *reinterpret_cast<__half2*>(&Ch[(size_t)r0 * N + col]) =
                    __floats2half2_rn(v0, v1);
            if (r1 < M)
                *reinterpret_cast<__half2*>(&Ch[(size_t)r1 * N + col]) =
                    __floats2half2_rn(v2, v3);
        }
    }
}

// ---- fused proj head (fp16): proj = relu(A@fc1+b1)@fc2 + b2, H in smem ----
__global__ __launch_bounds__(256) void k_proj16(
    int M,
    const __half* __restrict__ A,
    const __half* __restrict__ f1t,
    const float* __restrict__ fc1b,
    const __half* __restrict__ f2t,
    const float* __restrict__ fc2b,
    float* __restrict__ C)
{
    constexpr int BK = 32, LDS = 40, LDH = 136, K = 128, N = 128;
    extern __shared__ __half sm[];
    __half* As = sm;
    __half* Bs = As + 2 * 128 * LDS;
    __half* H  = Bs + 2 * 128 * LDS;

    const int tid  = threadIdx.x;
    const int lane = tid & 31;
    const int wid  = tid >> 5;
    const int g    = lane >> 2;
    const int t    = lane & 3;
    const int warpM = (wid & 1) * 64;
    const int warpN = (wid >> 1) * 32;
    const int gRow = blockIdx.y * 128;

    auto issueA = [&](int k0, int s) {
#pragma unroll
        for (int i = 0; i < 2; i++) {
            int idx = tid + i * 256;
            int m = idx >> 2, kq = (idx & 3) << 3;
            int gm = gRow + m;
            cp16(&As[s * 128 * LDS + m * LDS + kq], &A[(size_t)gm * K + k0 + kq], gm < M);
        }
    };
    auto issueB = [&](const __half* Bt, int k0, int s) {
#pragma unroll
        for (int i = 0; i < 2; i++) {
            int idx = tid + i * 256;
            int nn = idx >> 2, kq = (idx & 3) << 3;
            cp16(&Bs[s * 128 * LDS + nn * LDS + kq], &Bt[(size_t)nn * K + k0 + kq], true);
        }
    };

    float c[4][4][4];
    auto zeroC = [&]() {
#pragma unroll
        for (int mt = 0; mt < 4; mt++)
#pragma unroll
            for (int nt = 0; nt < 4; nt++)
#pragma unroll
                for (int i = 0; i < 4; i++) c[mt][nt][i] = 0.f;
    };

    const int T = K / BK;

    // stage 1: H = relu(A @ fc1 + fc1b)
    zeroC();
    issueA(0, 0); issueB(f1t, 0, 0);
    CP_COMMIT;
    for (int it = 0; it < T; it++) {
        int s = it & 1;
        if (it + 1 < T) {
            issueA((it + 1) * BK, s ^ 1); issueB(f1t, (it + 1) * BK, s ^ 1);
            CP_COMMIT; CP_WAIT(1);
        } else CP_WAIT(0);
        __syncthreads();
#pragma unroll
        for (int kk = 0; kk < BK; kk += 16) {
            uint32_t af[4][4], bf[4][2];
#pragma unroll
            for (int mt = 0; mt < 4; mt++) {
                int m0 = warpM + mt * 16 + g;
                const __half* Ab = &As[s * 128 * LDS];
                af[mt][0] = lds32h(&Ab[(m0    ) * LDS + kk + 2 * t    ]);
                af[mt][1] = lds32h(&Ab[(m0 + 8) * LDS + kk + 2 * t    ]);
                af[mt][2] = lds32h(&Ab[(m0    ) * LDS + kk + 2 * t + 8]);
                af[mt][3] = lds32h(&Ab[(m0 + 8) * LDS + kk + 2 * t + 8]);
            }
#pragma unroll
            for (int nt = 0; nt < 4; nt++) {
                int n0 = warpN + nt * 8 + g;
                const __half* Bb = &Bs[s * 128 * LDS];
                bf[nt][0] = lds32h(&Bb[n0 * LDS + kk + 2 * t    ]);
                bf[nt][1] = lds32h(&Bb[n0 * LDS + kk + 2 * t + 8]);
            }
#pragma unroll
            for (int mt = 0; mt < 4; mt++)
#pragma unroll
                for (int nt = 0; nt < 4; nt++)
                    mma_f16(c[mt][nt], af[mt], bf[nt]);
        }
        __syncthreads();
    }
#pragma unroll
    for (int mt = 0; mt < 4; mt++) {
        int m0 = warpM + mt * 16 + g;
#pragma unroll
        for (int nt = 0; nt < 4; nt++) {
            int col = warpN + nt * 8 + t * 2;
            float b0 = fc1b[col], b1 = fc1b[col + 1];
            float v0 = fmaxf(c[mt][nt][0] + b0, 0.f);
            float v1 = fmaxf(c[mt][nt][1] + b1, 0.f);
            float v2 = fmaxf(c[mt][nt][2] + b0, 0.f);
            float v3 = fmaxf(c[mt][nt][3] + b1, 0.f);
            *reinterpret_cast<__half2*>(&H[(m0    ) * LDH + col]) = __floats2half2_rn(v0, v1);
            *reinterpret_cast<__half2*>(&H[(m0 + 8) * LDH + col]) = __floats2half2_rn(v2, v3);
        }
    }
    __syncthreads();

    // stage 2: C = H @ fc2 + fc2b
    zeroC();
    issueB(f2t, 0, 0);
    CP_COMMIT;
    for (int it = 0; it < T; it++) {
        int s = it & 1;
        if (it + 1 < T) {
            issueB(f2t, (it + 1) * BK, s ^ 1);
            CP_COMMIT; CP_WAIT(1);
        } else CP_WAIT(0);
        __syncthreads();
        int kbase = it * BK;
#pragma unroll
        for (int kk = 0; kk < BK; kk += 16) {
            uint32_t af[4][4], bf[4][2];
#pragma unroll
            for (int mt = 0; mt < 4; mt++) {
                int m0 = warpM + mt * 16 + g;
                af[mt][0] = lds32h(&H[(m0    ) * LDH + kbase + kk + 2 * t    ]);
                af[mt][1] = lds32h(&H[(m0 + 8) * LDH + kbase + kk + 2 * t    ]);
                af[mt][2] = lds32h(&H[(m0    ) * LDH + kbase + kk + 2 * t + 8]);
                af[mt][3] = lds32h(&H[(m0 + 8) * LDH + kbase + kk + 2 * t + 8]);
            }
#pragma unroll
            for (int nt = 0; nt < 4; nt++) {
                int n0 = warpN + nt * 8 + g;
                const __half* Bb = &Bs[s * 128 * LDS];
                bf[nt][0] = lds32h(&Bb[n0 * LDS + kk + 2 * t    ]);
                bf[nt][1] = lds32h(&Bb[n0 * LDS + kk + 2 * t + 8]);
            }
#pragma unroll
            for (int mt = 0; mt < 4; mt++)
#pragma unroll
                for (int nt = 0; nt < 4; nt++)
                    mma_f16(c[mt][nt], af[mt], bf[nt]);
        }
        __syncthreads();
    }
#pragma unroll
    for (int mt = 0; mt < 4; mt++) {
        int r0 = gRow + warpM + mt * 16 + g;
        int r1 = r0 + 8;
#pragma unroll
        for (int nt = 0; nt < 4; nt++) {
            int col = warpN + nt * 8 + t * 2;
            float b0 = fc2b[col], b1 = fc2b[col + 1];
            if (r0 < M)
                *reinterpret_cast<float2*>(&C[(size_t)r0 * N + col]) =
                    make_float2(c[mt][nt][0] + b0, c[mt][nt][1] + b1);
            if (r1 < M)
                *reinterpret_cast<float2*>(&C[(size_t)r1 * N + col]) =
                    make_float2(c[mt][nt][2] + b0, c[mt][nt][3] + b1);
        }
    }
}

// ---------------- launch ----------------
extern "C" void kernel_launch(void* const* d_in, const int* in_sizes, int n_in,
                              void* d_out, int out_size) {
    const float* x    = (const float*)d_in[0];
    const int*   ei   = (const int*)d_in[1];
    const float* W1   = (const float*)d_in[2];
    const float* b1   = (const float*)d_in[3];
    const float* W2   = (const float*)d_in[4];
    const float* b2   = (const float*)d_in[5];
    const float* a    = (const float*)d_in[6];
    const float* fc1w = (const float*)d_in[7];
    const float* fc1b = (const float*)d_in[8];
    const float* fc2w = (const float*)d_in[9];
    const float* fc2b = (const float*)d_in[10];

    const int N = in_sizes[0] / 128;      // 100000 nodes
    const int E = in_sizes[1] / 2;        // 1600000 edges
    const int* src = ei;
    const int* dst = ei + E;

    float* out  = (float*)d_out;                    // [N,128]
    float* proj = out + (size_t)N * 128;            // [N,128]

    float* pd;
    __half *ph16, *pa16, *po116, *pw16;
    int *pdeg, *pexcl, *pbtot, *prowp, *pcur, *pcsrc;
    cudaGetSymbolAddress((void**)&pd,    g_dinv);
    cudaGetSymbolAddress((void**)&ph16,  g_h16);
    cudaGetSymbolAddress((void**)&pa16,  g_a16);
    cudaGetSymbolAddress((void**)&po116, g_o116);
    cudaGetSymbolAddress((void**)&pw16,  g_w16);
    cudaGetSymbolAddress((void**)&pdeg,  g_deg);
    cudaGetSymbolAddress((void**)&pexcl, g_excl);
    cudaGetSymbolAddress((void**)&pbtot, g_btot);
    cudaGetSymbolAddress((void**)&prowp, g_rowp);
    cudaGetSymbolAddress((void**)&pcur,  g_cur);
    cudaGetSymbolAddress((void**)&pcsrc, g_csrc);

    const int TPB = 256;
    const int nb  = (N + SCAN_B - 1) / SCAN_B;
    const int aggBlocks = (N * 32 + TPB - 1) / TPB;
    const int finBlocks = (N + 7) / 8;               // 8 nodes (warps) per block
    const int projSmem = (2 * 128 * 40 * 2 + 128 * 136) * 2;

    cudaFuncSetAttribute(k_proj16, cudaFuncAttributeMaxDynamicSharedMemorySize, projSmem);

    // ---- CSR build + weight convert + prescaled f2h (fused) ----
    k_hist_wconv<<<(E + TPB - 1) / TPB, TPB>>>(dst, pdeg, E, W1, W2, fc1w, fc2w, pw16);
    k_scan_blocks<<<nb, SCAN_B>>>(pdeg, pexcl, pbtot, N);
    k_finalize_f2h<<<finBlocks, TPB>>>(pdeg, pexcl, pbtot, prowp, pcur, pd, x, ph16, N, nb);
    k_fillcsr<<<(E + TPB - 1) / TPB, TPB>>>(src, dst, pcur, pcsrc, E);

    dim3 grid1(2, (N + 127) / 128);
    dim3 grid2(1, (N + 127) / 128);

    // ---- layer 1 ----
    k_agg16<false><<<aggBlocks, TPB>>>(prowp, pcsrc, pd, ph16, pa16,
                                       nullptr, nullptr, nullptr, N);
    tgemm16<1><<<grid1, 256>>>(N, 256, 128, pa16, pw16 + W1T_OFF, b1, a, nullptr, po116);

    // ---- layer 2 ----
    tgemm16<5><<<grid2, 256>>>(N, 128, 256, po116, pw16 + W2T_OFF, nullptr, nullptr, pd, ph16);
    k_agg16<true><<<aggBlocks, TPB>>>(prowp, pcsrc, pd, ph16, pa16,
                                      b2, a, out, N);

    // ---- fused proj head ----
    k_proj16<<<grid2, 256, projSmem>>>(N, pa16, pw16 + F1T_OFF, fc1b,
                                       pw16 + F2T_OFF, fc2b, proj);
}

// round 17
// speedup vs baseline: 1.2223x; 1.0045x over previous
#include <cuda_runtime.h>
#include <cuda_fp16.h>
#include <cstdint>

// ---------------- static scratch (no allocations allowed) ----------------
#define MAXN 100000
#define MAXE 1600000
#define SCAN_B 1024

__device__ float  g_dinv[MAXN];
__device__ __half g_h16 [MAXN * 128];     // prescaled gather buffer (x, then h2)
__device__ __half g_a16 [MAXN * 128];     // agg1 out ; later final-out fp16 mirror
__device__ __half g_o116[MAXN * 256];     // layer-1 output (fp16)
__device__ __half g_w16 [98304];          // transposed fp16 weights
__device__ int    g_deg [MAXN];           // zero at entry; re-zeroed in k_finalize
__device__ int    g_excl[MAXN];
__device__ int    g_btot[128];
__device__ int    g_rowp[MAXN + 1];
__device__ int    g_rank[MAXE];           // per-edge within-node rank (from hist)
__device__ int    g_csrc[MAXE];

#define W1T_OFF 0          // [256][128]
#define W2T_OFF 32768      // [128][256]
#define F1T_OFF 65536      // [128][128]
#define F2T_OFF 81920      // [128][128]

// ---- histogram (returns rank!) + weight convert/transpose ----
__global__ void k_hist_wconv(const int* __restrict__ dst, int* deg, int* rank, int E,
                             const float* __restrict__ W1, const float* __restrict__ W2,
                             const float* __restrict__ f1, const float* __restrict__ f2,
                             __half* __restrict__ w) {
    int i = blockIdx.x * blockDim.x + threadIdx.x;
    if (i < E) rank[i] = atomicAdd(&deg[dst[i]], 1);
    if (i < 32768) {                       // W1 [128][256]
        int k = i >> 8, n = i & 255;
        w[W1T_OFF + n * 128 + k] = __float2half_rn(W1[i]);
    } else if (i < 65536) {                // W2 [256][128]
        int j = i - 32768;
        int k = j >> 7, n = j & 127;
        w[W2T_OFF + n * 256 + k] = __float2half_rn(W2[j]);
    } else if (i < 81920) {                // fc1 [128][128]
        int j = i - 65536;
        int k = j >> 7, n = j & 127;
        w[F1T_OFF + n * 128 + k] = __float2half_rn(f1[j]);
    } else if (i < 98304) {                // fc2 [128][128]
        int j = i - 81920;
        int k = j >> 7, n = j & 127;
        w[F2T_OFF + n * 128 + k] = __float2half_rn(f2[j]);
    }
}

__global__ void k_scan_blocks(const int* __restrict__ deg, int* excl,
                              int* btot, int n) {
    __shared__ int sh[SCAN_B];
    int t = threadIdx.x;
    int i = blockIdx.x * SCAN_B + t;
    int v = (i < n) ? deg[i] : 0;
    sh[t] = v;
    __syncthreads();
    for (int off = 1; off < SCAN_B; off <<= 1) {
        int add = (t >= off) ? sh[t - off] : 0;
        __syncthreads();
        sh[t] += add;
        __syncthreads();
    }
    if (i < n) excl[i] = sh[t] - v;
    if (t == SCAN_B - 1) btot[blockIdx.x] = sh[t];
}

// ---- fused finalize: rowp/dinv/deg-reset + prescaled f2h, warp per node ----
__global__ void k_finalize_f2h(int* deg, const int* __restrict__ excl,
                               const int* __restrict__ btot,
                               int* rowp, float* dinv,
                               const float* __restrict__ x, __half* __restrict__ xh,
                               int n, int nb) {
    __shared__ int red[128];
    __shared__ int sOff;
    int t = threadIdx.x;
    int need = (blockIdx.x * 8) >> 10;
    if (t < 128) red[t] = (t < need && t < nb) ? btot[t] : 0;
    __syncthreads();
    for (int off = 64; off > 0; off >>= 1) {
        if (t < off) red[t] += red[t + off];
        __syncthreads();
    }
    if (t == 0) sOff = red[0];
    __syncthreads();

    int w = t >> 5, lane = t & 31;
    int d = blockIdx.x * 8 + w;
    if (d >= n) return;

    float di = 0.f;
    if (lane == 0) {
        int dg = deg[d];
        int rp = excl[d] + sOff;
        rowp[d] = rp;
        di = rsqrtf((float)dg + 1.0f);
        dinv[d] = di;
        if (d == n - 1) rowp[n] = rp + dg;
        deg[d] = 0;
    }
    di = __shfl_sync(0xffffffffu, di, 0);

    float4 v = reinterpret_cast<const float4*>(x + (size_t)d * 128)[lane];
    __half2 p0 = __floats2half2_rn(v.x * di, v.y * di);
    __half2 p1 = __floats2half2_rn(v.z * di, v.w * di);
    uint2 r;
    r.x = *reinterpret_cast<uint32_t*>(&p0);
    r.y = *reinterpret_cast<uint32_t*>(&p1);
    reinterpret_cast<uint2*>(xh + (size_t)d * 128)[lane] = r;
}

// ---- CSR fill WITHOUT atomics: pos = rowp[dst] + rank ----
__global__ void k_fillcsr(const int* __restrict__ src, const int* __restrict__ dst,
                          const int* __restrict__ rowp, const int* __restrict__ rank,
                          int* __restrict__ csrc, int E) {
    int e = blockIdx.x * blockDim.x + threadIdx.x;
    if (e >= E) return;
    csrc[rowp[dst[e]] + rank[e]] = src[e];
}

// -------- CSR aggregation (prescaled fp16 rows), warp per dst node --------
template <bool FINAL>
__global__ void k_agg16(const int* __restrict__ rowp, const int* __restrict__ csrc,
                        const float* __restrict__ dinv, const __half* __restrict__ h,
                        __half* __restrict__ outh,
                        const float* __restrict__ bias, const float* __restrict__ ap,
                        float* __restrict__ outf, int n) {
    int gtid = blockIdx.x * blockDim.x + threadIdx.x;
    int d = gtid >> 5, lane = gtid & 31;
    if (d >= n) return;

    float4 acc;
    {
        uint2 r = reinterpret_cast<const uint2*>(h + (size_t)d * 128)[lane];
        __half2 p0 = *reinterpret_cast<__half2*>(&r.x);
        __half2 p1 = *reinterpret_cast<__half2*>(&r.y);
        float2 f0 = __half22float2(p0), f1 = __half22float2(p1);
        acc = make_float4(f0.x, f0.y, f1.x, f1.y);
    }

    int j = rowp[d], end = rowp[d + 1];
    for (; j + 8 <= end; j += 8) {
        int s[8];
#pragma unroll
        for (int u = 0; u < 8; u++) s[u] = csrc[j + u];
        uint2 r[8];
#pragma unroll
        for (int u = 0; u < 8; u++)
            r[u] = reinterpret_cast<const uint2*>(h + (size_t)s[u] * 128)[lane];
#pragma unroll
        for (int u = 0; u < 8; u++) {
            __half2 p0 = *reinterpret_cast<__half2*>(&r[u].x);
            __half2 p1 = *reinterpret_cast<__half2*>(&r[u].y);
            float2 f0 = __half22float2(p0), f1 = __half22float2(p1);
            acc.x += f0.x; acc.y += f0.y; acc.z += f1.x; acc.w += f1.y;
        }
    }
    if (j + 4 <= end) {
        int s[4];
#pragma unroll
        for (int u = 0; u < 4; u++) s[u] = csrc[j + u];
        uint2 r[4];
#pragma unroll
        for (int u = 0; u < 4; u++)
            r[u] = reinterpret_cast<const uint2*>(h + (size_t)s[u] * 128)[lane];
#pragma unroll
        for (int u = 0; u < 4; u++) {
            __half2 p0 = *reinterpret_cast<__half2*>(&r[u].x);
            __half2 p1 = *reinterpret_cast<__half2*>(&r[u].y);
            float2 f0 = __half22float2(p0), f1 = __half22float2(p1);
            acc.x += f0.x; acc.y += f0.y; acc.z += f1.x; acc.w += f1.y;
        }
        j += 4;
    }
    for (; j < end; j++) {
        uint2 r = reinterpret_cast<const uint2*>(h + (size_t)csrc[j] * 128)[lane];
        __half2 p0 = *reinterpret_cast<__half2*>(&r.x);
        __half2 p1 = *reinterpret_cast<__half2*>(&r.y);
        float2 f0 = __half22float2(p0), f1 = __half22float2(p1);
        acc.x += f0.x; acc.y += f0.y; acc.z += f1.x; acc.w += f1.y;
    }

    float dd = dinv[d];
    acc.x *= dd; acc.y *= dd; acc.z *= dd; acc.w *= dd;

    if (FINAL) {
        float a = *ap;
        float4 bb = reinterpret_cast<const float4*>(bias)[lane];
        acc.x += bb.x; acc.y += bb.y; acc.z += bb.z; acc.w += bb.w;
        acc.x = acc.x >= 0.f ? acc.x : a * acc.x;
        acc.y = acc.y >= 0.f ? acc.y : a * acc.y;
        acc.z = acc.z >= 0.f ? acc.z : a * acc.z;
        acc.w = acc.w >= 0.f ? acc.w : a * acc.w;
        reinterpret_cast<float4*>(outf + (size_t)d * 128)[lane] = acc;
    }
    __half2 q0 = __floats2half2_rn(acc.x, acc.y);
    __half2 q1 = __floats2half2_rn(acc.z, acc.w);
    uint2 o;
    o.x = *reinterpret_cast<uint32_t*>(&q0);
    o.y = *reinterpret_cast<uint32_t*>(&q1);
    reinterpret_cast<uint2*>(outh + (size_t)d * 128)[lane] = o;
}

// ------------- fp16 tensor-core GEMM (m16n8k16), cp.async 2-stage -------------
__device__ __forceinline__ void mma_f16(float* c, const uint32_t* a, const uint32_t* b) {
    asm volatile(
        "mma.sync.aligned.m16n8k16.row.col.f32.f16.f16.f32 "
        "{%0,%1,%2,%3}, {%4,%5,%6,%7}, {%8,%9}, {%0,%1,%2,%3};"
        : "+f"(c[0]), "+f"(c[1]), "+f"(c[2]), "+f"(c[3])
        : "r"(a[0]), "r"(a[1]), "r"(a[2]), "r"(a[3]),
          "r"(b[0]), "r"(b[1]));
}

__device__ __forceinline__ void cp16(void* smem_dst, const void* gsrc, bool valid) {
    uint32_t saddr = (uint32_t)__cvta_generic_to_shared(smem_dst);
    int sz = valid ? 16 : 0;
    asm volatile("cp.async.cg.shared.global [%0], [%1], 16, %2;"
                 :: "r"(saddr), "l"(gsrc), "r"(sz));
}
#define CP_COMMIT asm volatile("cp.async.commit_group;")
#define CP_WAIT(n) asm volatile("cp.async.wait_group %0;" :: "n"(n))

__device__ __forceinline__ uint32_t lds32h(const __half* p) {
    return *reinterpret_cast<const uint32_t*>(p);
}

// A: [M][K] fp16 row-major. Bt: [N][K] fp16 (pre-transposed).
// EPI 1: fp16(prelu(acc+bias)) -> Ch.   EPI 5: fp16(acc*dinv[row]) -> Ch.
template <int EPI>
__global__ __launch_bounds__(256) void tgemm16(
    int M, int N, int K,
    const __half* __restrict__ A, const __half* __restrict__ Bt,
    const float* __restrict__ bias, const float* __restrict__ prelu_a,
    const float* __restrict__ dinvp,
    __half* __restrict__ Ch)
{
    constexpr int BK = 32;
    constexpr int LDS = 40;
    __shared__ __half As[2][128 * LDS];
    __shared__ __half Bs[2][128 * LDS];

    const int tid  = threadIdx.x;
    const int lane = tid & 31;
    const int wid  = tid >> 5;
    const int g    = lane >> 2;
    const int t    = lane & 3;

    const int warpM = (wid & 1) * 64;
    const int warpN = (wid >> 1) * 32;

    const int gRow = blockIdx.y * 128;
    const int gCol = blockIdx.x * 128;

    auto issueTile = [&](int k0, int s) {
#pragma unroll
        for (int i = 0; i < 2; i++) {
            int idx = tid + i * 256;
            int m  = idx >> 2, kq = (idx & 3) << 3;
            int gm = gRow + m;
            cp16(&As[s][m * LDS + kq], &A[(size_t)gm * K + k0 + kq], gm < M);
        }
#pragma unroll
        for (int i = 0; i < 2; i++) {
            int idx = tid + i * 256;
            int nn = idx >> 2, kq = (idx & 3) << 3;
            cp16(&Bs[s][nn * LDS + kq], &Bt[(size_t)(gCol + nn) * K + k0 + kq], true);
        }
    };

    float c[4][4][4];
#pragma unroll
    for (int mt = 0; mt < 4; mt++)
#pragma unroll
        for (int nt = 0; nt < 4; nt++)
#pragma unroll
            for (int i = 0; i < 4; i++) c[mt][nt][i] = 0.f;

    const int T = K / BK;
    issueTile(0, 0);
    CP_COMMIT;

    for (int it = 0; it < T; it++) {
        int s = it & 1;
        if (it + 1 < T) {
            issueTile((it + 1) * BK, s ^ 1);
            CP_COMMIT;
            CP_WAIT(1);
        } else {
            CP_WAIT(0);
        }
        __syncthreads();

#pragma unroll
        for (int kk = 0; kk < BK; kk += 16) {
            uint32_t af[4][4], bf[4][2];
#pragma unroll
            for (int mt = 0; mt < 4; mt++) {
                int m0 = warpM + mt * 16 + g;
                const __half* Ab = &As[s][0];
                af[mt][0] = lds32h(&Ab[(m0    ) * LDS + kk + 2 * t    ]);
                af[mt][1] = lds32h(&Ab[(m0 + 8) * LDS + kk + 2 * t    ]);
                af[mt][2] = lds32h(&Ab[(m0    ) * LDS + kk + 2 * t + 8]);
                af[mt][3] = lds32h(&Ab[(m0 + 8) * LDS + kk + 2 * t + 8]);
            }
#pragma unroll
            for (int nt = 0; nt < 4; nt++) {
                int n0 = warpN + nt * 8 + g;
                const __half* Bb = &Bs[s][0];
                bf[nt][0] = lds32h(&Bb[n0 * LDS + kk + 2 * t    ]);
                bf[nt][1] = lds32h(&Bb[n0 * LDS + kk + 2 * t + 8]);
            }
#pragma unroll
            for (int mt = 0; mt < 4; mt++)
#pragma unroll
                for (int nt = 0; nt < 4; nt++)
                    mma_f16(c[mt][nt], af[mt], bf[nt]);
        }
        __syncthreads();
    }

    float a_val = 0.f;
    if (EPI == 1) a_val = *prelu_a;

#pragma unroll
    for (int mt = 0; mt < 4; mt++) {
        int r0 = gRow + warpM + mt * 16 + g;
        int r1 = r0 + 8;
        float s0 = 1.f, s1 = 1.f;
        if (EPI == 5) {
            if (r0 < M) s0 = dinvp[r0];
            if (r1 < M) s1 = dinvp[r1];
        }
#pragma unroll
        for (int nt = 0; nt < 4; nt++) {
            int col = gCol + warpN + nt * 8 + t * 2;
            float v0 = c[mt][nt][0], v1 = c[mt][nt][1];
            float v2 = c[mt][nt][2], v3 = c[mt][nt][3];

            if (EPI == 1) {
                float b0 = bias[col], b1 = bias[col + 1];
                v0 += b0; v1 += b1; v2 += b0; v3 += b1;
                v0 = v0 >= 0.f ? v0 : a_val * v0;
                v1 = v1 >= 0.f ? v1 : a_val * v1;
                v2 = v2 >= 0.f ? v2 : a_val * v2;
                v3 = v3 >= 0.f ? v3 : a_val * v3;
            }
            if (EPI == 5) { v0 *= s0; v1 *= s0; v2 *= s1; v3 *= s1; }

            if (r0 < M)
                *reinterpret_cast<__half2*>(&Ch[(size_t)r0 * N + col]) =
                    __floats2half2_rn(v0, v1);
            if (r1 < M)
                *reinterpret_cast<__half2*>(&Ch[(size_t)r1 * N + col]) =
                    __floats2half2_rn(v2, v3);
        }
    }
}

// ---- fused proj head (fp16): proj = relu(A@fc1+b1)@fc2 + b2, H in smem ----
__global__ __launch_bounds__(256) void k_proj16(
    int M,
    const __half* __restrict__ A,
    const __half* __restrict__ f1t,
    const float* __restrict__ fc1b,
    const __half* __restrict__ f2t,
    const float* __restrict__ fc2b,
    float* __restrict__ C)
{
    constexpr int BK = 32, LDS = 40, LDH = 136, K = 128, N = 128;
    extern __shared__ __half sm[];
    __half* As = sm;
    __half* Bs = As + 2 * 128 * LDS;
    __half* H  = Bs + 2 * 128 * LDS;

    const int tid  = threadIdx.x;
    const int lane = tid & 31;
    const int wid  = tid >> 5;
    const int g    = lane >> 2;
    const int t    = lane & 3;
    const int warpM = (wid & 1) * 64;
    const int warpN = (wid >> 1) * 32;
    const int gRow = blockIdx.y * 128;

    auto issueA = [&](int k0, int s) {
#pragma unroll
        for (int i = 0; i < 2; i++) {
            int idx = tid + i * 256;
            int m = idx >> 2, kq = (idx & 3) << 3;
            int gm = gRow + m;
            cp16(&As[s * 128 * LDS + m * LDS + kq], &A[(size_t)gm * K + k0 + kq], gm < M);
        }
    };
    auto issueB = [&](const __half* Bt, int k0, int s) {
#pragma unroll
        for (int i = 0; i < 2; i++) {
            int idx = tid + i * 256;
            int nn = idx >> 2, kq = (idx & 3) << 3;
            cp16(&Bs[s * 128 * LDS + nn * LDS + kq], &Bt[(size_t)nn * K + k0 + kq], true);
        }
    };

    float c[4][4][4];
    auto zeroC = [&]() {
#pragma unroll
        for (int mt = 0; mt < 4; mt++)
#pragma unroll
            for (int nt = 0; nt < 4; nt++)
#pragma unroll
                for (int i = 0; i < 4; i++) c[mt][nt][i] = 0.f;
    };

    const int T = K / BK;

    // stage 1: H = relu(A @ fc1 + fc1b)
    zeroC();
    issueA(0, 0); issueB(f1t, 0, 0);
    CP_COMMIT;
    for (int it = 0; it < T; it++) {
        int s = it & 1;
        if (it + 1 < T) {
            issueA((it + 1) * BK, s ^ 1); issueB(f1t, (it + 1) * BK, s ^ 1);
            CP_COMMIT; CP_WAIT(1);
        } else CP_WAIT(0);
        __syncthreads();
#pragma unroll
        for (int kk = 0; kk < BK; kk += 16) {
            uint32_t af[4][4], bf[4][2];
#pragma unroll
            for (int mt = 0; mt < 4; mt++) {
                int m0 = warpM + mt * 16 + g;
                const __half* Ab = &As[s * 128 * LDS];
                af[mt][0] = lds32h(&Ab[(m0    ) * LDS + kk + 2 * t    ]);
                af[mt][1] = lds32h(&Ab[(m0 + 8) * LDS + kk + 2 * t    ]);
                af[mt][2] = lds32h(&Ab[(m0    ) * LDS + kk + 2 * t + 8]);
                af[mt][3] = lds32h(&Ab[(m0 + 8) * LDS + kk + 2 * t + 8]);
            }
#pragma unroll
            for (int nt = 0; nt < 4; nt++) {
                int n0 = warpN + nt * 8 + g;
                const __half* Bb = &Bs[s * 128 * LDS];
                bf[nt][0] = lds32h(&Bb[n0 * LDS + kk + 2 * t    ]);
                bf[nt][1] = lds32h(&Bb[n0 * LDS + kk + 2 * t + 8]);
            }
#pragma unroll
            for (int mt = 0; mt < 4; mt++)
#pragma unroll
                for (int nt = 0; nt < 4; nt++)
                    mma_f16(c[mt][nt], af[mt], bf[nt]);
        }
        __syncthreads();
    }
#pragma unroll
    for (int mt = 0; mt < 4; mt++) {
        int m0 = warpM + mt * 16 + g;
#pragma unroll
        for (int nt = 0; nt < 4; nt++) {
            int col = warpN + nt * 8 + t * 2;
            float b0 = fc1b[col], b1 = fc1b[col + 1];
            float v0 = fmaxf(c[mt][nt][0] + b0, 0.f);
            float v1 = fmaxf(c[mt][nt][1] + b1, 0.f);
            float v2 = fmaxf(c[mt][nt][2] + b0, 0.f);
            float v3 = fmaxf(c[mt][nt][3] + b1, 0.f);
            *reinterpret_cast<__half2*>(&H[(m0    ) * LDH + col]) = __floats2half2_rn(v0, v1);
            *reinterpret_cast<__half2*>(&H[(m0 + 8) * LDH + col]) = __floats2half2_rn(v2, v3);
        }
    }
    __syncthreads();

    // stage 2: C = H @ fc2 + fc2b
    zeroC();
    issueB(f2t, 0, 0);
    CP_COMMIT;
    for (int it = 0; it < T; it++) {
        int s = it & 1;
        if (it + 1 < T) {
            issueB(f2t, (it + 1) * BK, s ^ 1);
            CP_COMMIT; CP_WAIT(1);
        } else CP_WAIT(0);
        __syncthreads();
        int kbase = it * BK;
#pragma unroll
        for (int kk = 0; kk < BK; kk += 16) {
            uint32_t af[4][4], bf[4][2];
#pragma unroll
            for (int mt = 0; mt < 4; mt++) {
                int m0 = warpM + mt * 16 + g;
                af[mt][0] = lds32h(&H[(m0    ) * LDH + kbase + kk + 2 * t    ]);
                af[mt][1] = lds32h(&H[(m0 + 8) * LDH + kbase + kk + 2 * t    ]);
                af[mt][2] = lds32h(&H[(m0    ) * LDH + kbase + kk + 2 * t + 8]);
                af[mt][3] = lds32h(&H[(m0 + 8) * LDH + kbase + kk + 2 * t + 8]);
            }
#pragma unroll
            for (int nt = 0; nt < 4; nt++) {
                int n0 = warpN + nt * 8 + g;
                const __half* Bb = &Bs[s * 128 * LDS];
                bf[nt][0] = lds32h(&Bb[n0 * LDS + kk + 2 * t    ]);
                bf[nt][1] = lds32h(&Bb[n0 * LDS + kk + 2 * t + 8]);
            }
#pragma unroll
            for (int mt = 0; mt < 4; mt++)
#pragma unroll
                for (int nt = 0; nt < 4; nt++)
                    mma_f16(c[mt][nt], af[mt], bf[nt]);
        }
        __syncthreads();
    }
#pragma unroll
    for (int mt = 0; mt < 4; mt++) {
        int r0 = gRow + warpM + mt * 16 + g;
        int r1 = r0 + 8;
#pragma unroll
        for (int nt = 0; nt < 4; nt++) {
            int col = warpN + nt * 8 + t * 2;
            float b0 = fc2b[col], b1 = fc2b[col + 1];
            if (r0 < M)
                *reinterpret_cast<float2*>(&C[(size_t)r0 * N + col]) =
                    make_float2(c[mt][nt][0] + b0, c[mt][nt][1] + b1);
            if (r1 < M)
                *reinterpret_cast<float2*>(&C[(size_t)r1 * N + col]) =
                    make_float2(c[mt][nt][2] + b0, c[mt][nt][3] + b1);
        }
    }
}

// ---------------- launch ----------------
extern "C" void kernel_launch(void* const* d_in, const int* in_sizes, int n_in,
                              void* d_out, int out_size) {
    const float* x    = (const float*)d_in[0];
    const int*   ei   = (const int*)d_in[1];
    const float* W1   = (const float*)d_in[2];
    const float* b1   = (const float*)d_in[3];
    const float* W2   = (const float*)d_in[4];
    const float* b2   = (const float*)d_in[5];
    const float* a    = (const float*)d_in[6];
    const float* fc1w = (const float*)d_in[7];
    const float* fc1b = (const float*)d_in[8];
    const float* fc2w = (const float*)d_in[9];
    const float* fc2b = (const float*)d_in[10];

    const int N = in_sizes[0] / 128;      // 100000 nodes
    const int E = in_sizes[1] / 2;        // 1600000 edges
    const int* src = ei;
    const int* dst = ei + E;

    float* out  = (float*)d_out;                    // [N,128]
    float* proj = out + (size_t)N * 128;            // [N,128]

    float* pd;
    __half *ph16, *pa16, *po116, *pw16;
    int *pdeg, *pexcl, *pbtot, *prowp, *prank, *pcsrc;
    cudaGetSymbolAddress((void**)&pd,    g_dinv);
    cudaGetSymbolAddress((void**)&ph16,  g_h16);
    cudaGetSymbolAddress((void**)&pa16,  g_a16);
    cudaGetSymbolAddress((void**)&po116, g_o116);
    cudaGetSymbolAddress((void**)&pw16,  g_w16);
    cudaGetSymbolAddress((void**)&pdeg,  g_deg);
    cudaGetSymbolAddress((void**)&pexcl, g_excl);
    cudaGetSymbolAddress((void**)&pbtot, g_btot);
    cudaGetSymbolAddress((void**)&prowp, g_rowp);
    cudaGetSymbolAddress((void**)&prank, g_rank);
    cudaGetSymbolAddress((void**)&pcsrc, g_csrc);

    const int TPB = 256;
    const int nb  = (N + SCAN_B - 1) / SCAN_B;
    const int aggBlocks = (N * 32 + TPB - 1) / TPB;
    const int finBlocks = (N + 7) / 8;
    const int projSmem = (2 * 128 * 40 * 2 + 128 * 136) * 2;

    cudaFuncSetAttribute(k_proj16, cudaFuncAttributeMaxDynamicSharedMemorySize, projSmem);

    // ---- CSR build (rank captured in hist) + weight convert + f2h ----
    k_hist_wconv<<<(E + TPB - 1) / TPB, TPB>>>(dst, pdeg, prank, E,
                                               W1, W2, fc1w, fc2w, pw16);
    k_scan_blocks<<<nb, SCAN_B>>>(pdeg, pexcl, pbtot, N);
    k_finalize_f2h<<<finBlocks, TPB>>>(pdeg, pexcl, pbtot, prowp, pd, x, ph16, N, nb);
    k_fillcsr<<<(E + TPB - 1) / TPB, TPB>>>(src, dst, prowp, prank, pcsrc, E);

    dim3 grid1(2, (N + 127) / 128);
    dim3 grid2(1, (N + 127) / 128);

    // ---- layer 1 ----
    k_agg16<false><<<aggBlocks, TPB>>>(prowp, pcsrc, pd, ph16, pa16,
                                       nullptr, nullptr, nullptr, N);
    tgemm16<1><<<grid1, 256>>>(N, 256, 128, pa16, pw16 + W1T_OFF, b1, a, nullptr, po116);

    // ---- layer 2 ----
    tgemm16<5><<<grid2, 256>>>(N, 128, 256, po116, pw16 + W2T_OFF, nullptr, nullptr, pd, ph16);
    k_agg16<true><<<aggBlocks, TPB>>>(prowp, pcsrc, pd, ph16, pa16,
                                      b2, a, out, N);

    // ---- fused proj head ----
    k_proj16<<<grid2, 256, projSmem>>>(N, pa16, pw16 + F1T_OFF, fc1b,
                                       pw16 + F2T_OFF, fc2b, proj);
}